// round 15
// baseline (speedup 1.0000x reference)
#include <cuda_runtime.h>
#include <cuda_bf16.h>
#include <math.h>
#include <stdint.h>

#define VP 196
#define TLN 316
#define SQ 512
#define VD 1024
#define HDIM 768
#define NHEAD 8
#define HD 96
#define FFD 3072
#define NLAYER 6
#define NB 16
#define MROWS (NB*SQ)   /* 8192 */

typedef __nv_bfloat16 bf16;

// ---------------- weight split buffers (hi/lo bf16), one big arena ----------
#define OFF_VPW  0
#define OFF_TPW  786432
#define OFF_INW  1376256
#define OFF_OUTW 11993088
#define OFF_VW1  15532032
#define OFF_LW1  29687808
#define OFF_VW2  43843584
#define OFF_LW2  57999360
#define W_TOTAL  72155136

__device__ __align__(256) bf16 g_wh[W_TOTAL];
__device__ __align__(256) bf16 g_wl[W_TOTAL];

// ---------------- activation scratch ----------------
__device__ __align__(256) float g_x[MROWS*HDIM];
__device__ __align__(256) float g_attn[MROWS*HDIM];
__device__ __align__(256) float g_ffn[MROWS*HDIM];
__device__ __align__(256) float g_bias[NB*SQ];

__device__ __align__(256) bf16 g_vish[3136*VD],  g_visl[3136*VD];
__device__ __align__(256) bf16 g_txth[5056*HDIM], g_txtl[5056*HDIM];
__device__ __align__(256) bf16 g_xh[MROWS*HDIM],  g_xl[MROWS*HDIM];
__device__ __align__(256) bf16 g_qkvh[MROWS*3*HDIM], g_qkvl[MROWS*3*HDIM];
__device__ __align__(256) bf16 g_vth[NB*NHEAD*HD*SQ], g_vtl[NB*NHEAD*HD*SQ];
__device__ __align__(256) bf16 g_yh[MROWS*HDIM],  g_yl[MROWS*HDIM];
__device__ __align__(256) bf16 g_hh[MROWS*FFD],   g_hl[MROWS*FFD];

// ---------------- helpers ----------------
__device__ __forceinline__ int rowmap(int i, int mode) {
    if (mode == 1) { int b = i / VP;  return b * SQ + (i - b * VP); }
    if (mode == 2) { int b = i / TLN; return b * SQ + VP + (i - b * TLN); }
    return i;
}

__device__ __forceinline__ float blkSum(float v, float* sh) {
    int lane = threadIdx.x & 31, w = threadIdx.x >> 5, nw = blockDim.x >> 5;
    #pragma unroll
    for (int o = 16; o > 0; o >>= 1) v += __shfl_xor_sync(0xffffffffu, v, o);
    if (lane == 0) sh[w] = v;
    __syncthreads();
    v = (threadIdx.x < nw) ? sh[threadIdx.x] : 0.f;
    if (w == 0) {
        #pragma unroll
        for (int o = 4; o > 0; o >>= 1) v += __shfl_xor_sync(0xffffffffu, v, o);
        if (lane == 0) sh[0] = v;
    }
    __syncthreads();
    v = sh[0];
    __syncthreads();
    return v;
}

// ---------------- fp32 -> bf16 hi/lo split (vectorized) ----------------
__global__ void cvt_split(const float4* __restrict__ src, bf16* __restrict__ H,
                          bf16* __restrict__ L, int n4) {
    int i = blockIdx.x * 256 + threadIdx.x;
    if (i >= n4) return;
    float4 v = src[i];
    bf16 h0 = __float2bfloat16_rn(v.x), h1 = __float2bfloat16_rn(v.y);
    bf16 h2 = __float2bfloat16_rn(v.z), h3 = __float2bfloat16_rn(v.w);
    *(__nv_bfloat162*)(H + 4*i)     = __halves2bfloat162(h0, h1);
    *(__nv_bfloat162*)(H + 4*i + 2) = __halves2bfloat162(h2, h3);
    bf16 l0 = __float2bfloat16_rn(v.x - __bfloat162float(h0));
    bf16 l1 = __float2bfloat16_rn(v.y - __bfloat162float(h1));
    bf16 l2 = __float2bfloat16_rn(v.z - __bfloat162float(h2));
    bf16 l3 = __float2bfloat16_rn(v.w - __bfloat162float(h3));
    *(__nv_bfloat162*)(L + 4*i)     = __halves2bfloat162(l0, l1);
    *(__nv_bfloat162*)(L + 4*i + 2) = __halves2bfloat162(l2, l3);
}

// ================= shared asm wrappers =================
__device__ __forceinline__ void mma_bf16(float* c, const uint32_t* a, const uint32_t* b) {
    asm volatile(
        "mma.sync.aligned.m16n8k16.row.col.f32.bf16.bf16.f32 "
        "{%0,%1,%2,%3}, {%4,%5,%6,%7}, {%8,%9}, {%0,%1,%2,%3};"
        : "+f"(c[0]), "+f"(c[1]), "+f"(c[2]), "+f"(c[3])
        : "r"(a[0]), "r"(a[1]), "r"(a[2]), "r"(a[3]), "r"(b[0]), "r"(b[1]));
}

__device__ __forceinline__ void cpa16(uint32_t saddr, const void* gptr) {
    asm volatile("cp.async.cg.shared.global [%0], [%1], 16;" :: "r"(saddr), "l"(gptr));
}

__device__ __forceinline__ void ldm4(uint32_t& r0, uint32_t& r1, uint32_t& r2,
                                     uint32_t& r3, uint32_t addr) {
    asm volatile("ldmatrix.sync.aligned.m8n8.x4.shared.b16 {%0,%1,%2,%3}, [%4];"
                 : "=r"(r0), "=r"(r1), "=r"(r2), "=r"(r3) : "r"(addr));
}

__device__ __forceinline__ void split2(float x, float y, uint32_t& H, uint32_t& L) {
    bf16 hx = __float2bfloat16_rn(x), hy = __float2bfloat16_rn(y);
    __nv_bfloat162 h2 = __halves2bfloat162(hx, hy);
    H = *(uint32_t*)&h2;
    __nv_bfloat162 l2 = __halves2bfloat162(
        __float2bfloat16_rn(x - __bfloat162float(hx)),
        __float2bfloat16_rn(y - __bfloat162float(hy)));
    L = *(uint32_t*)&l2;
}

// ================= split-bf16 GEMM core: 256x128 CTA tile =================
// 256 threads, warps 4x2, warp tile 64x64, BK=32 double-buffered cp.async.
#define GPQ 40                        /* row pitch in bf16 (80B) */
#define A_ARR (256*GPQ*2)             /* 20480 B */
#define B_ARR (128*GPQ*2)             /* 10240 B */
#define G_STG (2*A_ARR + 2*B_ARR)     /* 61440 B per stage */
#define SMEM_TOT (2*G_STG)            /* 122880 B */

__device__ __forceinline__ void gemm_core(
    int M, int N, int K,
    const bf16* __restrict__ Ah, const bf16* __restrict__ Al, int lda, int mapA,
    const bf16* __restrict__ Wh, const bf16* __restrict__ Wl, int ldw,
    const float* __restrict__ bz,
    float* __restrict__ Cf, bf16* __restrict__ Ch, bf16* __restrict__ Cl,
    int ldc, int mapC, int act, int m0, int n0)
{
    extern __shared__ __align__(128) bf16 smem[];
    int tid = threadIdx.x;
    int wid = tid >> 5, lane = tid & 31;
    int wm = wid >> 1, wn = wid & 1;          // warp origin (wm*64, wn*64)

    // staging: A row = tid (256 rows x 32 cols), B row = tid&127, half = tid>>7
    int arow = m0 + tid; if (arow >= M) arow = M - 1;
    int wrow = n0 + (tid & 127); if (wrow >= N) wrow = N - 1;
    const bf16* gA_h = Ah + (size_t)rowmap(arow, mapA) * lda;
    const bf16* gA_l = Al + (size_t)rowmap(arow, mapA) * lda;
    int bhalf = (tid >> 7) * 16;
    const bf16* gW_h = Wh + (size_t)wrow * ldw + bhalf;
    const bf16* gW_l = Wl + (size_t)wrow * ldw + bhalf;
    uint32_t s0 = (uint32_t)__cvta_generic_to_shared(smem);
    uint32_t sbA = (uint32_t)(tid * GPQ) * 2;
    uint32_t sbB = (uint32_t)((tid & 127) * GPQ + bhalf) * 2;

    float acc[32][4];
    #pragma unroll
    for (int i = 0; i < 32; i++)
        #pragma unroll
        for (int j = 0; j < 4; j++) acc[i][j] = 0.f;

    int aLaneRow = (lane & 7) + ((lane >> 3) & 1) * 8;
    int aLaneCol = (lane >> 4) * 8;
    int bLaneRow = (lane & 7) + (lane >> 4) * 8;
    int bLaneCol = ((lane >> 3) & 1) * 8;
    uint32_t aBase = s0 + (uint32_t)((wm * 64 + aLaneRow) * GPQ + aLaneCol) * 2;
    uint32_t bBase = s0 + 2 * A_ARR + (uint32_t)((wn * 64 + bLaneRow) * GPQ + bLaneCol) * 2;

    // prologue: stage 0 <- k=0
    #pragma unroll
    for (int c = 0; c < 4; c++) {
        cpa16(s0 + sbA + c * 16,          gA_h + c * 8);
        cpa16(s0 + A_ARR + sbA + c * 16,  gA_l + c * 8);
    }
    #pragma unroll
    for (int c = 0; c < 2; c++) {
        cpa16(s0 + 2 * A_ARR + sbB + c * 16,          gW_h + c * 8);
        cpa16(s0 + 2 * A_ARR + B_ARR + sbB + c * 16,  gW_l + c * 8);
    }
    asm volatile("cp.async.commit_group;");

    int stage = 0;
    for (int k0 = 0; k0 < K; k0 += 32) {
        bool more = (k0 + 32) < K;
        if (more) {
            uint32_t sn = s0 + (stage ^ 1) * G_STG;
            #pragma unroll
            for (int c = 0; c < 4; c++) {
                cpa16(sn + sbA + c * 16,         gA_h + k0 + 32 + c * 8);
                cpa16(sn + A_ARR + sbA + c * 16, gA_l + k0 + 32 + c * 8);
            }
            #pragma unroll
            for (int c = 0; c < 2; c++) {
                cpa16(sn + 2 * A_ARR + sbB + c * 16,         gW_h + k0 + 32 + c * 8);
                cpa16(sn + 2 * A_ARR + B_ARR + sbB + c * 16, gW_l + k0 + 32 + c * 8);
            }
            asm volatile("cp.async.commit_group;");
            asm volatile("cp.async.wait_group 1;");
        } else {
            asm volatile("cp.async.wait_group 0;");
        }
        __syncthreads();

        uint32_t stOff = stage * G_STG;
        #pragma unroll
        for (int ks = 0; ks < 2; ks++) {
            uint32_t kByte = (uint32_t)(ks * 16) * 2;
            // B fragments: 8 n-tiles (pairs via x4)
            uint32_t bh[8][2], bl[8][2];
            #pragma unroll
            for (int p = 0; p < 4; p++) {
                uint32_t ad = bBase + stOff + kByte + (uint32_t)(p * 16 * GPQ) * 2;
                ldm4(bh[2*p][0], bh[2*p][1], bh[2*p+1][0], bh[2*p+1][1], ad);
                ldm4(bl[2*p][0], bl[2*p][1], bl[2*p+1][0], bl[2*p+1][1], ad + B_ARR);
            }
            #pragma unroll
            for (int mt = 0; mt < 4; mt++) {
                uint32_t ad = aBase + stOff + kByte + (uint32_t)(mt * 16 * GPQ) * 2;
                uint32_t ah[4], al[4];
                ldm4(ah[0], ah[1], ah[2], ah[3], ad);
                ldm4(al[0], al[1], al[2], al[3], ad + A_ARR);
                #pragma unroll
                for (int nt = 0; nt < 8; nt++)
                    mma_bf16(acc[mt * 8 + nt], ah, bh[nt]);
                #pragma unroll
                for (int nt = 0; nt < 8; nt++)
                    mma_bf16(acc[mt * 8 + nt], ah, bl[nt]);
                #pragma unroll
                for (int nt = 0; nt < 8; nt++)
                    mma_bf16(acc[mt * 8 + nt], al, bh[nt]);
            }
        }
        __syncthreads();
        stage ^= 1;
    }

    int qr = lane >> 2;
    #pragma unroll
    for (int mt = 0; mt < 4; mt++) {
        #pragma unroll
        for (int nt = 0; nt < 8; nt++) {
            const float* c = acc[mt * 8 + nt];
            int r = m0 + wm * 64 + mt * 16 + qr;
            int cn = n0 + wn * 64 + nt * 8 + (lane & 3) * 2;
            if (cn >= N) continue;
            float bz0 = bz ? bz[cn] : 0.f;
            float bz1 = bz ? bz[cn + 1] : 0.f;
            #pragma unroll
            for (int half = 0; half < 2; half++) {
                int rr = r + half * 8;
                if (rr < M) {
                    float v0 = c[half * 2 + 0] + bz0;
                    float v1 = c[half * 2 + 1] + bz1;
                    if (act == 1) {
                        v0 = 0.5f * v0 * (1.f + erff(v0 * 0.70710678118654752f));
                        v1 = 0.5f * v1 * (1.f + erff(v1 * 0.70710678118654752f));
                    }
                    size_t idx = (size_t)rowmap(rr, mapC) * ldc + cn;
                    if (Cf) { Cf[idx] = v0; Cf[idx + 1] = v1; }
                    if (Ch) {
                        uint32_t H, L;
                        split2(v0, v1, H, L);
                        *(uint32_t*)(Ch + idx) = H;
                        *(uint32_t*)(Cl + idx) = L;
                    }
                }
            }
        }
    }
}

__global__ __launch_bounds__(256, 1) void gemm_tc(
    int M, int N, int K,
    const bf16* __restrict__ Ah, const bf16* __restrict__ Al, int lda, int mapA,
    const bf16* __restrict__ Wh, const bf16* __restrict__ Wl, int ldw,
    const float* __restrict__ bias,
    float* __restrict__ Cf, bf16* __restrict__ Ch, bf16* __restrict__ Cl,
    int ldc, int mapC, int act)
{
    gemm_core(M, N, K, Ah, Al, lda, mapA, Wh, Wl, ldw, bias,
              Cf, Ch, Cl, ldc, mapC, act, blockIdx.y * 256, blockIdx.x * 128);
}

__global__ __launch_bounds__(256, 1) void gemm_dual(
    int N, int act,
    int M0, int K0, const bf16* __restrict__ Ah0, const bf16* __restrict__ Al0,
    int lda0, int mapA0, const bf16* __restrict__ Wh0, const bf16* __restrict__ Wl0,
    const float* __restrict__ b0,
    int M1, int K1, const bf16* __restrict__ Ah1, const bf16* __restrict__ Al1,
    int lda1, int mapA1, const bf16* __restrict__ Wh1, const bf16* __restrict__ Wl1,
    const float* __restrict__ b1,
    float* __restrict__ Cf, bf16* __restrict__ Ch, bf16* __restrict__ Cl,
    int ldc, int mapC0, int mapC1)
{
    int z = blockIdx.z;
    int M   = z ? M1 : M0;
    int m0  = blockIdx.y * 256;
    if (m0 >= M) return;
    int K   = z ? K1 : K0;
    int lda = z ? lda1 : lda0;
    gemm_core(M, N, K,
              z ? Ah1 : Ah0, z ? Al1 : Al0, lda, z ? mapA1 : mapA0,
              z ? Wh1 : Wh0, z ? Wl1 : Wl0, K,
              z ? b1 : b0,
              Cf, Ch, Cl, ldc, z ? mapC1 : mapC0, act,
              m0, blockIdx.x * 128);
}

// ================= fused flash attention =================
#define FA_QP 104
#define FA_VPI 136
#define FA_OQH 0
#define FA_OQL 26624
#define FA_OKH 53248
#define FA_OKL 79872
#define FA_OVH 106496
#define FA_OVL 132608
#define FA_OBI 158720
#define FA_SMEM 160768

__global__ __launch_bounds__(256, 1) void flash_attn(
    const bf16* __restrict__ qkvh, const bf16* __restrict__ qkvl,
    const bf16* __restrict__ vth,  const bf16* __restrict__ vtl,
    const float* __restrict__ bias,
    bf16* __restrict__ yh, bf16* __restrict__ yl)
{
    extern __shared__ __align__(128) char fsm[];
    uint32_t s0 = (uint32_t)__cvta_generic_to_shared(fsm);
    int tid = threadIdx.x, wid = tid >> 5, lane = tid & 31;
    int z = blockIdx.z, b = z >> 3, h = z & 7;
    int q0 = blockIdx.x * 128;
    const float scale = 0.10206207261596575f;   // 1/sqrt(96)

    const bf16* gQh = qkvh + (size_t)b * SQ * (3*HDIM) + h * HD;
    const bf16* gQl = qkvl + (size_t)b * SQ * (3*HDIM) + h * HD;
    const bf16* gKh = gQh + HDIM;
    const bf16* gKl = gQl + HDIM;
    const bf16* gVh = vth + (size_t)z * HD * SQ;
    const bf16* gVl = vtl + (size_t)z * HD * SQ;

    if (tid < 128) {
        float4 bv = ((const float4*)(bias + b * SQ))[tid];
        ((float4*)(fsm + FA_OBI))[tid] = bv;
    }
    #pragma unroll
    for (int i = 0; i < 6; i++) {
        int id = tid + i * 256;
        int row = id / 12, cc = id % 12;
        uint32_t dst = s0 + (uint32_t)(row * (FA_QP*2) + cc * 16);
        const bf16* sh_ = gQh + (size_t)(q0 + row) * (3*HDIM) + cc * 8;
        const bf16* sl_ = gQl + (size_t)(q0 + row) * (3*HDIM) + cc * 8;
        cpa16(dst + FA_OQH, sh_);
        cpa16(dst + FA_OQL, sl_);
    }
    asm volatile("cp.async.commit_group;");

    int aLaneRow = (lane & 7) + ((lane >> 3) & 1) * 8;
    int aLaneCol = (lane >> 4) * 8;
    int bLaneRow = (lane & 7) + (lane >> 4) * 8;
    int bLaneCol = ((lane >> 3) & 1) * 8;
    uint32_t aQ = s0 + (uint32_t)((wid * 16 + aLaneRow) * (FA_QP*2) + aLaneCol * 2);
    uint32_t bK = s0 + (uint32_t)(bLaneRow * (FA_QP*2) + bLaneCol * 2);
    uint32_t bV = s0 + (uint32_t)(bLaneRow * (FA_VPI*2) + bLaneCol * 2);

    int g = lane >> 2, t2 = (lane & 3) * 2;
    const float* sbias = (const float*)(fsm + FA_OBI);

    float o[12][4];
    #pragma unroll
    for (int j = 0; j < 12; j++)
        #pragma unroll
        for (int k = 0; k < 4; k++) o[j][k] = 0.f;
    float m0 = -1e30f, m1 = -1e30f, l0 = 0.f, l1 = 0.f;

    for (int kb = 0; kb < 4; kb++) {
        #pragma unroll
        for (int i = 0; i < 6; i++) {
            int id = tid + i * 256;
            int krow = id / 12, kcc = id % 12;
            uint32_t dst = s0 + (uint32_t)(krow * (FA_QP*2) + kcc * 16);
            const bf16* sh_ = gKh + (size_t)(kb * 128 + krow) * (3*HDIM) + kcc * 8;
            const bf16* sl_ = gKl + (size_t)(kb * 128 + krow) * (3*HDIM) + kcc * 8;
            cpa16(dst + FA_OKH, sh_);
            cpa16(dst + FA_OKL, sl_);
            int vrow = id / 16, vcc = id % 16;
            uint32_t vdst = s0 + (uint32_t)(vrow * (FA_VPI*2) + vcc * 16);
            const bf16* vh_ = gVh + (size_t)vrow * SQ + kb * 128 + vcc * 8;
            const bf16* vl_ = gVl + (size_t)vrow * SQ + kb * 128 + vcc * 8;
            cpa16(vdst + FA_OVH, vh_);
            cpa16(vdst + FA_OVL, vl_);
        }
        asm volatile("cp.async.commit_group;");
        asm volatile("cp.async.wait_group 0;");
        __syncthreads();

        float sc[16][4];
        #pragma unroll
        for (int j = 0; j < 16; j++)
            #pragma unroll
            for (int k = 0; k < 4; k++) sc[j][k] = 0.f;
        #pragma unroll
        for (int s = 0; s < 6; s++) {
            uint32_t ah[4], al[4];
            ldm4(ah[0], ah[1], ah[2], ah[3], aQ + FA_OQH + s * 32);
            ldm4(al[0], al[1], al[2], al[3], aQ + FA_OQL + s * 32);
            #pragma unroll
            for (int p = 0; p < 8; p++) {
                uint32_t bh[4], bl[4];
                uint32_t ad = bK + (uint32_t)(p * 16 * (FA_QP*2)) + s * 32;
                ldm4(bh[0], bh[1], bh[2], bh[3], ad + FA_OKH);
                ldm4(bl[0], bl[1], bl[2], bl[3], ad + FA_OKL);
                mma_bf16(sc[2*p],   ah, &bh[0]);
                mma_bf16(sc[2*p+1], ah, &bh[2]);
                mma_bf16(sc[2*p],   ah, &bl[0]);
                mma_bf16(sc[2*p+1], ah, &bl[2]);
                mma_bf16(sc[2*p],   al, &bh[0]);
                mma_bf16(sc[2*p+1], al, &bh[2]);
            }
        }

        float mx0 = -1e30f, mx1 = -1e30f;
        #pragma unroll
        for (int j = 0; j < 16; j++) {
            int col = kb * 128 + j * 8 + t2;
            float bz0 = sbias[col], bz1 = sbias[col + 1];
            sc[j][0] = sc[j][0] * scale + bz0;
            sc[j][1] = sc[j][1] * scale + bz1;
            sc[j][2] = sc[j][2] * scale + bz0;
            sc[j][3] = sc[j][3] * scale + bz1;
            mx0 = fmaxf(mx0, fmaxf(sc[j][0], sc[j][1]));
            mx1 = fmaxf(mx1, fmaxf(sc[j][2], sc[j][3]));
        }
        mx0 = fmaxf(mx0, __shfl_xor_sync(0xffffffffu, mx0, 1));
        mx0 = fmaxf(mx0, __shfl_xor_sync(0xffffffffu, mx0, 2));
        mx1 = fmaxf(mx1, __shfl_xor_sync(0xffffffffu, mx1, 1));
        mx1 = fmaxf(mx1, __shfl_xor_sync(0xffffffffu, mx1, 2));
        float mn0 = fmaxf(m0, mx0), mn1 = fmaxf(m1, mx1);
        float al0 = expf(m0 - mn0), al1 = expf(m1 - mn1);
        m0 = mn0; m1 = mn1;
        float sum0 = 0.f, sum1 = 0.f;
        #pragma unroll
        for (int j = 0; j < 16; j++) {
            sc[j][0] = expf(sc[j][0] - m0);
            sc[j][1] = expf(sc[j][1] - m0);
            sc[j][2] = expf(sc[j][2] - m1);
            sc[j][3] = expf(sc[j][3] - m1);
            sum0 += sc[j][0] + sc[j][1];
            sum1 += sc[j][2] + sc[j][3];
        }
        sum0 += __shfl_xor_sync(0xffffffffu, sum0, 1);
        sum0 += __shfl_xor_sync(0xffffffffu, sum0, 2);
        sum1 += __shfl_xor_sync(0xffffffffu, sum1, 1);
        sum1 += __shfl_xor_sync(0xffffffffu, sum1, 2);
        l0 = l0 * al0 + sum0;
        l1 = l1 * al1 + sum1;
        #pragma unroll
        for (int j = 0; j < 12; j++) {
            o[j][0] *= al0; o[j][1] *= al0; o[j][2] *= al1; o[j][3] *= al1;
        }

        #pragma unroll
        for (int s = 0; s < 8; s++) {
            uint32_t pah[4], pal[4];
            split2(sc[2*s][0],   sc[2*s][1],   pah[0], pal[0]);
            split2(sc[2*s][2],   sc[2*s][3],   pah[1], pal[1]);
            split2(sc[2*s+1][0], sc[2*s+1][1], pah[2], pal[2]);
            split2(sc[2*s+1][2], sc[2*s+1][3], pah[3], pal[3]);
            #pragma unroll
            for (int p = 0; p < 6; p++) {
                uint32_t bh[4], bl[4];
                uint32_t ad = bV + (uint32_t)(p * 16 * (FA_VPI*2)) + s * 32;
                ldm4(bh[0], bh[1], bh[2], bh[3], ad + FA_OVH);
                ldm4(bl[0], bl[1], bl[2], bl[3], ad + FA_OVL);
                mma_bf16(o[2*p],   pah, &bh[0]);
                mma_bf16(o[2*p+1], pah, &bh[2]);
                mma_bf16(o[2*p],   pah, &bl[0]);
                mma_bf16(o[2*p+1], pah, &bl[2]);
                mma_bf16(o[2*p],   pal, &bh[0]);
                mma_bf16(o[2*p+1], pal, &bh[2]);
            }
        }
        __syncthreads();
    }

    float inv0 = 1.f / l0, inv1 = 1.f / l1;
    int r0 = q0 + wid * 16 + g;
    size_t row0 = (size_t)(b * SQ + r0) * HDIM + h * HD;
    size_t row1 = row0 + 8 * HDIM;
    #pragma unroll
    for (int j = 0; j < 12; j++) {
        int d = j * 8 + t2;
        uint32_t H, L;
        split2(o[j][0] * inv0, o[j][1] * inv0, H, L);
        *(uint32_t*)(yh + row0 + d) = H;
        *(uint32_t*)(yl + row0 + d) = L;
        split2(o[j][2] * inv1, o[j][3] * inv1, H, L);
        *(uint32_t*)(yh + row1 + d) = H;
        *(uint32_t*)(yl + row1 + d) = L;
    }
}

// ---------------- V transpose ----------------
__global__ void transposeV(const bf16* __restrict__ qh, const bf16* __restrict__ ql,
                           bf16* __restrict__ vth, bf16* __restrict__ vtl)
{
    __shared__ bf16 th[32][33], tl[32][33];
    int z = blockIdx.z, b = z >> 3, h = z & 7;
    size_t qbase = (size_t)b * SQ * (3 * HDIM) + 2 * HDIM + h * HD;
    int d0 = blockIdx.x * 32, k0 = blockIdx.y * 32;
    int tx = threadIdx.x;
    for (int i = threadIdx.y; i < 32; i += 8) {
        size_t s = qbase + (size_t)(k0 + i) * (3 * HDIM) + d0 + tx;
        th[i][tx] = qh[s];
        tl[i][tx] = ql[s];
    }
    __syncthreads();
    size_t obase = (size_t)z * HD * SQ;
    for (int i = threadIdx.y; i < 32; i += 8) {
        size_t s = obase + (size_t)(d0 + i) * SQ + k0 + tx;
        vth[s] = th[tx][i];
        vtl[s] = tl[tx][i];
    }
}

// ---------------- residual + LayerNorm, writes fp32 + split-bf16 ----------
__global__ void ln_row(const float* __restrict__ a, const float* __restrict__ res,
                       const float* __restrict__ g1, const float* __restrict__ b1,
                       const float* __restrict__ g2, const float* __restrict__ b2,
                       float* __restrict__ out, bf16* __restrict__ outH,
                       bf16* __restrict__ outL)
{
    __shared__ float sh[8];
    int m = blockIdx.x;
    int s = m & (SQ - 1);
    const float* gg = (s < VP) ? g1 : g2;
    const float* bb = (s < VP) ? b1 : b2;
    const float* ar = a + (size_t)m * HDIM;
    const float* rr = res ? res + (size_t)m * HDIM : nullptr;
    int t = threadIdx.x;  // 256
    float v[3];
    float sum = 0.f;
    #pragma unroll
    for (int i = 0; i < 3; i++) {
        float xv = ar[t + i * 256];
        if (rr) xv += rr[t + i * 256];
        v[i] = xv; sum += xv;
    }
    float mean = blkSum(sum, sh) * (1.f / HDIM);
    float sq = 0.f;
    #pragma unroll
    for (int i = 0; i < 3; i++) { float d = v[i] - mean; sq += d * d; }
    float var = blkSum(sq, sh) * (1.f / HDIM);
    float inv = rsqrtf(var + 1e-5f);
    size_t ob = (size_t)m * HDIM;
    #pragma unroll
    for (int i = 0; i < 3; i++) {
        int c = t + i * 256;
        float o = (v[i] - mean) * inv * gg[c] + bb[c];
        out[ob + c] = o;
        bf16 hi = __float2bfloat16_rn(o);
        outH[ob + c] = hi;
        outL[ob + c] = __float2bfloat16_rn(o - __bfloat162float(hi));
    }
}

// ---------------- key padding bias (mask as 4-byte words) ----------------
__global__ void build_bias(const int* __restrict__ mask, float* __restrict__ bias) {
    int i = blockIdx.x * 256 + threadIdx.x;
    if (i < NB * SQ) {
        int s = i & (SQ - 1);
        float v = 0.f;
        if (s >= VP) {
            int b = i >> 9;
            v = (mask[b * TLN + (s - VP)] != 0) ? 0.f : -1e30f;
        }
        bias[i] = v;
    }
}

// ---------------- final output ----------------
__global__ void write_out(const float* __restrict__ x, const int* __restrict__ mask,
                          float* __restrict__ out, int out_size) {
    int n = blockIdx.x * 256 + threadIdx.x;
    if (n >= out_size) return;
    const int NX = MROWS * HDIM;
    if (n < NX) {
        out[n] = x[n];
    } else {
        int idx = n - NX;
        if (idx < NB * SQ) {
            int s = idx & (SQ - 1);
            int b = idx >> 9;
            out[n] = (s < VP) ? 1.f : ((mask[b * TLN + (s - VP)] != 0) ? 1.f : 0.f);
        }
    }
}

// ---------------- host ----------------
static inline void split(const float* src, bf16* h, bf16* l, long long n) {
    int n4 = (int)(n / 4);
    cvt_split<<<(n4 + 255) / 256, 256>>>((const float4*)src, h, l, n4);
}

extern "C" void kernel_launch(void* const* d_in, const int* in_sizes, int n_in,
                              void* d_out, int out_size) {
    (void)in_sizes; (void)n_in;
    static int smem_set = 0;
    if (!smem_set) {
        cudaFuncSetAttribute(gemm_tc,    cudaFuncAttributeMaxDynamicSharedMemorySize, SMEM_TOT);
        cudaFuncSetAttribute(gemm_dual,  cudaFuncAttributeMaxDynamicSharedMemorySize, SMEM_TOT);
        cudaFuncSetAttribute(flash_attn, cudaFuncAttributeMaxDynamicSharedMemorySize, FA_SMEM);
        smem_set = 1;
    }
    const float* vis   = (const float*)d_in[0];
    const float* txt   = (const float*)d_in[1];
    const int*   mask  = (const int*)d_in[2];
    const float* vp_w = (const float*)d_in[3];
    const float* vp_b = (const float*)d_in[4];
    const float* vp_g = (const float*)d_in[5];
    const float* vp_be= (const float*)d_in[6];
    const float* tp_w = (const float*)d_in[7];
    const float* tp_b = (const float*)d_in[8];
    const float* tp_g = (const float*)d_in[9];
    const float* tp_be= (const float*)d_in[10];
    const float* in_w = (const float*)d_in[11];
    const float* in_b = (const float*)d_in[12];
    const float* out_w= (const float*)d_in[13];
    const float* out_b= (const float*)d_in[14];
    const float* ln1g = (const float*)d_in[15];
    const float* ln1b = (const float*)d_in[16];
    const float* vew1 = (const float*)d_in[17];
    const float* veb1 = (const float*)d_in[18];
    const float* vew2 = (const float*)d_in[19];
    const float* veb2 = (const float*)d_in[20];
    const float* lew1 = (const float*)d_in[21];
    const float* leb1 = (const float*)d_in[22];
    const float* lew2 = (const float*)d_in[23];
    const float* leb2 = (const float*)d_in[24];
    const float* ln2g = (const float*)d_in[25];
    const float* ln2b = (const float*)d_in[26];

    float *x, *attn, *ffn, *bias;
    bf16 *wh, *wl, *vish, *visl, *txth, *txtl, *xh, *xl, *qh, *ql;
    bf16 *vth, *vtl, *yh, *yl, *hh, *hl;
    cudaGetSymbolAddress((void**)&x,    g_x);
    cudaGetSymbolAddress((void**)&attn, g_attn);
    cudaGetSymbolAddress((void**)&ffn,  g_ffn);
    cudaGetSymbolAddress((void**)&bias, g_bias);
    cudaGetSymbolAddress((void**)&wh,   g_wh);
    cudaGetSymbolAddress((void**)&wl,   g_wl);
    cudaGetSymbolAddress((void**)&vish, g_vish);
    cudaGetSymbolAddress((void**)&visl, g_visl);
    cudaGetSymbolAddress((void**)&txth, g_txth);
    cudaGetSymbolAddress((void**)&txtl, g_txtl);
    cudaGetSymbolAddress((void**)&xh,   g_xh);
    cudaGetSymbolAddress((void**)&xl,   g_xl);
    cudaGetSymbolAddress((void**)&qh,   g_qkvh);
    cudaGetSymbolAddress((void**)&ql,   g_qkvl);
    cudaGetSymbolAddress((void**)&vth,  g_vth);
    cudaGetSymbolAddress((void**)&vtl,  g_vtl);
    cudaGetSymbolAddress((void**)&yh,   g_yh);
    cudaGetSymbolAddress((void**)&yl,   g_yl);
    cudaGetSymbolAddress((void**)&hh,   g_hh);
    cudaGetSymbolAddress((void**)&hl,   g_hl);

    // ---- prologue ----
    build_bias<<<32, 256>>>(mask, bias);
    split(vis,   vish, visl, (long long)3136 * VD);
    split(txt,   txth, txtl, (long long)5056 * HDIM);
    split(vp_w,  wh + OFF_VPW,  wl + OFF_VPW,  (long long)HDIM * VD);
    split(tp_w,  wh + OFF_TPW,  wl + OFF_TPW,  (long long)HDIM * HDIM);

    // merged input projections (vision z=0, text z=1) -> x (mapped rows)
    gemm_dual<<<dim3(6, 20, 2), 256, SMEM_TOT>>>(HDIM, 0,
        3136, VD,   vish, visl, VD,   0, wh + OFF_VPW, wl + OFF_VPW, vp_b,
        5056, HDIM, txth, txtl, HDIM, 0, wh + OFF_TPW, wl + OFF_TPW, tp_b,
        x, nullptr, nullptr, HDIM, 1, 2);

    split(in_w,  wh + OFF_INW,  wl + OFF_INW,  (long long)NLAYER * 3 * HDIM * HDIM);
    split(out_w, wh + OFF_OUTW, wl + OFF_OUTW, (long long)NLAYER * HDIM * HDIM);
    split(vew1,  wh + OFF_VW1,  wl + OFF_VW1,  (long long)NLAYER * FFD * HDIM);
    split(lew1,  wh + OFF_LW1,  wl + OFF_LW1,  (long long)NLAYER * FFD * HDIM);
    split(vew2,  wh + OFF_VW2,  wl + OFF_VW2,  (long long)NLAYER * HDIM * FFD);
    split(lew2,  wh + OFF_LW2,  wl + OFF_LW2,  (long long)NLAYER * HDIM * FFD);

    ln_row<<<MROWS, 256>>>(x, nullptr, vp_g, vp_be, tp_g, tp_be, x, xh, xl);

    for (int i = 0; i < NLAYER; i++) {
        const bf16* iwh = wh + OFF_INW  + (size_t)i * 3 * HDIM * HDIM;
        const bf16* iwl = wl + OFF_INW  + (size_t)i * 3 * HDIM * HDIM;
        const bf16* owh = wh + OFF_OUTW + (size_t)i * HDIM * HDIM;
        const bf16* owl = wl + OFF_OUTW + (size_t)i * HDIM * HDIM;
        const bf16* v1h = wh + OFF_VW1  + (size_t)i * FFD * HDIM;
        const bf16* v1l = wl + OFF_VW1  + (size_t)i * FFD * HDIM;
        const bf16* l1h = wh + OFF_LW1  + (size_t)i * FFD * HDIM;
        const bf16* l1l = wl + OFF_LW1  + (size_t)i * FFD * HDIM;
        const bf16* v2h = wh + OFF_VW2  + (size_t)i * HDIM * FFD;
        const bf16* v2l = wl + OFF_VW2  + (size_t)i * HDIM * FFD;
        const bf16* l2h = wh + OFF_LW2  + (size_t)i * HDIM * FFD;
        const bf16* l2l = wl + OFF_LW2  + (size_t)i * HDIM * FFD;
        const float* ib  = in_b  + (size_t)i * 3 * HDIM;
        const float* ob  = out_b + (size_t)i * HDIM;
        const float* g1  = ln1g + (size_t)i * HDIM;
        const float* be1 = ln1b + (size_t)i * HDIM;
        const float* g2  = ln2g + (size_t)i * HDIM;
        const float* be2 = ln2b + (size_t)i * HDIM;
        const float* vb1 = veb1 + (size_t)i * FFD;
        const float* vb2 = veb2 + (size_t)i * HDIM;
        const float* lb1 = leb1 + (size_t)i * FFD;
        const float* lb2 = leb2 + (size_t)i * HDIM;

        // QKV projection -> split bf16
        gemm_tc<<<dim3(18, 32), 256, SMEM_TOT>>>(MROWS, 3 * HDIM, HDIM,
            xh, xl, HDIM, 0, iwh, iwl, HDIM, ib,
            nullptr, qh, ql, 3 * HDIM, 0, 0);

        transposeV<<<dim3(3, 16, NB * NHEAD), dim3(32, 8)>>>(qh, ql, vth, vtl);

        // fused attention: scores + softmax + P·V
        flash_attn<<<dim3(4, 1, NB * NHEAD), 256, FA_SMEM>>>(qh, ql, vth, vtl,
                                                             bias, yh, yl);

        // out projection -> fp32
        gemm_tc<<<dim3(6, 32), 256, SMEM_TOT>>>(MROWS, HDIM, HDIM,
            yh, yl, HDIM, 0, owh, owl, HDIM, ob,
            attn, nullptr, nullptr, HDIM, 0, 0);

        ln_row<<<MROWS, 256>>>(x, attn, g1, be1, g1, be1, x, xh, xl);

        // dual-expert FFN (GELU) merged launches
        gemm_dual<<<dim3(24, 20, 2), 256, SMEM_TOT>>>(FFD, 1,
            3136, HDIM, xh, xl, HDIM, 1, v1h, v1l, vb1,
            5056, HDIM, xh, xl, HDIM, 2, l1h, l1l, lb1,
            nullptr, hh, hl, FFD, 1, 2);
        gemm_dual<<<dim3(6, 20, 2), 256, SMEM_TOT>>>(HDIM, 0,
            3136, FFD, hh, hl, FFD, 1, v2h, v2l, vb2,
            5056, FFD, hh, hl, FFD, 2, l2h, l2l, lb2,
            ffn, nullptr, nullptr, HDIM, 1, 2);

        ln_row<<<MROWS, 256>>>(x, ffn, g2, be2, g2, be2, x, xh, xl);
    }

    write_out<<<(out_size + 255) / 256, 256>>>(x, mask, (float*)d_out, out_size);
}

// round 16
// speedup vs baseline: 1.1706x; 1.1706x over previous
#include <cuda_runtime.h>
#include <cuda_bf16.h>
#include <math.h>
#include <stdint.h>

#define VP 196
#define TLN 316
#define SQ 512
#define VD 1024
#define HDIM 768
#define NHEAD 8
#define HD 96
#define FFD 3072
#define NLAYER 6
#define NB 16
#define MROWS (NB*SQ)   /* 8192 */

typedef __nv_bfloat16 bf16;

// ---------------- weight split buffers (hi/lo bf16), one big arena ----------
#define OFF_VPW  0
#define OFF_TPW  786432
#define OFF_INW  1376256
#define OFF_OUTW 11993088
#define OFF_VW1  15532032
#define OFF_LW1  29687808
#define OFF_VW2  43843584
#define OFF_LW2  57999360
#define W_TOTAL  72155136

__device__ __align__(256) bf16 g_wh[W_TOTAL];
__device__ __align__(256) bf16 g_wl[W_TOTAL];

// ---------------- activation scratch ----------------
__device__ __align__(256) float g_x[MROWS*HDIM];
__device__ __align__(256) float g_attn[MROWS*HDIM];
__device__ __align__(256) float g_ffn[MROWS*HDIM];
__device__ __align__(256) float g_bias[NB*SQ];

__device__ __align__(256) bf16 g_vish[3136*VD],  g_visl[3136*VD];
__device__ __align__(256) bf16 g_txth[5056*HDIM], g_txtl[5056*HDIM];
__device__ __align__(256) bf16 g_xh[MROWS*HDIM],  g_xl[MROWS*HDIM];
__device__ __align__(256) bf16 g_qkvh[MROWS*3*HDIM], g_qkvl[MROWS*3*HDIM];
__device__ __align__(256) bf16 g_vth[NB*NHEAD*HD*SQ], g_vtl[NB*NHEAD*HD*SQ];
__device__ __align__(256) bf16 g_yh[MROWS*HDIM],  g_yl[MROWS*HDIM];
__device__ __align__(256) bf16 g_hh[MROWS*FFD],   g_hl[MROWS*FFD];

// ---------------- helpers ----------------
__device__ __forceinline__ int rowmap(int i, int mode) {
    if (mode == 1) { int b = i / VP;  return b * SQ + (i - b * VP); }
    if (mode == 2) { int b = i / TLN; return b * SQ + VP + (i - b * TLN); }
    return i;
}

__device__ __forceinline__ float blkSum(float v, float* sh) {
    int lane = threadIdx.x & 31, w = threadIdx.x >> 5, nw = blockDim.x >> 5;
    #pragma unroll
    for (int o = 16; o > 0; o >>= 1) v += __shfl_xor_sync(0xffffffffu, v, o);
    if (lane == 0) sh[w] = v;
    __syncthreads();
    v = (threadIdx.x < nw) ? sh[threadIdx.x] : 0.f;
    if (w == 0) {
        #pragma unroll
        for (int o = 4; o > 0; o >>= 1) v += __shfl_xor_sync(0xffffffffu, v, o);
        if (lane == 0) sh[0] = v;
    }
    __syncthreads();
    v = sh[0];
    __syncthreads();
    return v;
}

// ---------------- fp32 -> bf16 hi/lo split (vectorized) ----------------
__global__ void cvt_split(const float4* __restrict__ src, bf16* __restrict__ H,
                          bf16* __restrict__ L, int n4) {
    int i = blockIdx.x * 256 + threadIdx.x;
    if (i >= n4) return;
    float4 v = src[i];
    bf16 h0 = __float2bfloat16_rn(v.x), h1 = __float2bfloat16_rn(v.y);
    bf16 h2 = __float2bfloat16_rn(v.z), h3 = __float2bfloat16_rn(v.w);
    *(__nv_bfloat162*)(H + 4*i)     = __halves2bfloat162(h0, h1);
    *(__nv_bfloat162*)(H + 4*i + 2) = __halves2bfloat162(h2, h3);
    bf16 l0 = __float2bfloat16_rn(v.x - __bfloat162float(h0));
    bf16 l1 = __float2bfloat16_rn(v.y - __bfloat162float(h1));
    bf16 l2 = __float2bfloat16_rn(v.z - __bfloat162float(h2));
    bf16 l3 = __float2bfloat16_rn(v.w - __bfloat162float(h3));
    *(__nv_bfloat162*)(L + 4*i)     = __halves2bfloat162(l0, l1);
    *(__nv_bfloat162*)(L + 4*i + 2) = __halves2bfloat162(l2, l3);
}

// ================= shared asm wrappers =================
__device__ __forceinline__ void mma_bf16(float* c, const uint32_t* a, const uint32_t* b) {
    asm volatile(
        "mma.sync.aligned.m16n8k16.row.col.f32.bf16.bf16.f32 "
        "{%0,%1,%2,%3}, {%4,%5,%6,%7}, {%8,%9}, {%0,%1,%2,%3};"
        : "+f"(c[0]), "+f"(c[1]), "+f"(c[2]), "+f"(c[3])
        : "r"(a[0]), "r"(a[1]), "r"(a[2]), "r"(a[3]), "r"(b[0]), "r"(b[1]));
}

__device__ __forceinline__ void cpa16(uint32_t saddr, const void* gptr) {
    asm volatile("cp.async.cg.shared.global [%0], [%1], 16;" :: "r"(saddr), "l"(gptr));
}

__device__ __forceinline__ void ldm4(uint32_t& r0, uint32_t& r1, uint32_t& r2,
                                     uint32_t& r3, uint32_t addr) {
    asm volatile("ldmatrix.sync.aligned.m8n8.x4.shared.b16 {%0,%1,%2,%3}, [%4];"
                 : "=r"(r0), "=r"(r1), "=r"(r2), "=r"(r3) : "r"(addr));
}

__device__ __forceinline__ void split2(float x, float y, uint32_t& H, uint32_t& L) {
    bf16 hx = __float2bfloat16_rn(x), hy = __float2bfloat16_rn(y);
    __nv_bfloat162 h2 = __halves2bfloat162(hx, hy);
    H = *(uint32_t*)&h2;
    __nv_bfloat162 l2 = __halves2bfloat162(
        __float2bfloat16_rn(x - __bfloat162float(hx)),
        __float2bfloat16_rn(y - __bfloat162float(hy)));
    L = *(uint32_t*)&l2;
}

// ================= split-bf16 GEMM core: 128x128 tile, 2 CTA/SM =================
#define SBQ 40
#define ARRB (128*SBQ*2)
#define STGB (4*ARRB)
#define SMEM_TOT (2*STGB)

__device__ __forceinline__ void gemm_core(
    int M, int N, int K,
    const bf16* __restrict__ Ah, const bf16* __restrict__ Al, int lda, int mapA,
    const bf16* __restrict__ Wh, const bf16* __restrict__ Wl, int ldw,
    const float* __restrict__ bz,
    float* __restrict__ Cf, bf16* __restrict__ Ch, bf16* __restrict__ Cl,
    int ldc, int mapC, int act, int m0, int n0,
    bf16* __restrict__ Vth, bf16* __restrict__ Vtl)   // V-transpose fusion (QKV only)
{
    extern __shared__ __align__(128) bf16 smem[];
    int tid = threadIdx.x;
    int wid = tid >> 5, lane = tid & 31;
    int wm = wid >> 2, wn = wid & 3;

    int lrow = tid & 127;
    int c0 = (tid >> 7) * 16;
    int arow = m0 + lrow; if (arow >= M) arow = M - 1;
    int wrow = n0 + lrow; if (wrow >= N) wrow = N - 1;
    const bf16* gA_h = Ah + (size_t)rowmap(arow, mapA) * lda + c0;
    const bf16* gA_l = Al + (size_t)rowmap(arow, mapA) * lda + c0;
    const bf16* gW_h = Wh + (size_t)wrow * ldw + c0;
    const bf16* gW_l = Wl + (size_t)wrow * ldw + c0;
    uint32_t s0 = (uint32_t)__cvta_generic_to_shared(smem);
    uint32_t sb = (uint32_t)(lrow * SBQ + c0) * 2;

    float acc[16][4];
    #pragma unroll
    for (int i = 0; i < 16; i++)
        #pragma unroll
        for (int j = 0; j < 4; j++) acc[i][j] = 0.f;

    int aLaneRow = (lane & 7) + ((lane >> 3) & 1) * 8;
    int aLaneCol = (lane >> 4) * 8;
    int bLaneRow = (lane & 7) + (lane >> 4) * 8;
    int bLaneCol = ((lane >> 3) & 1) * 8;
    uint32_t aBase = s0 + (uint32_t)((wm * 64 + aLaneRow) * SBQ + aLaneCol) * 2;
    uint32_t bBase = s0 + 2 * ARRB + (uint32_t)((wn * 32 + bLaneRow) * SBQ + bLaneCol) * 2;

    #pragma unroll
    for (int ar = 0; ar < 4; ar++) {
        const bf16* g = (ar == 0) ? gA_h : (ar == 1) ? gA_l : (ar == 2) ? gW_h : gW_l;
        cpa16(s0 + ar * ARRB + sb,      g);
        cpa16(s0 + ar * ARRB + sb + 16, g + 8);
    }
    asm volatile("cp.async.commit_group;");

    int stage = 0;
    for (int k0 = 0; k0 < K; k0 += 32) {
        bool more = (k0 + 32) < K;
        if (more) {
            uint32_t sn = s0 + (stage ^ 1) * STGB;
            #pragma unroll
            for (int ar = 0; ar < 4; ar++) {
                const bf16* g = ((ar == 0) ? gA_h : (ar == 1) ? gA_l :
                                 (ar == 2) ? gW_h : gW_l) + k0 + 32;
                cpa16(sn + ar * ARRB + sb,      g);
                cpa16(sn + ar * ARRB + sb + 16, g + 8);
            }
            asm volatile("cp.async.commit_group;");
            asm volatile("cp.async.wait_group 1;");
        } else {
            asm volatile("cp.async.wait_group 0;");
        }
        __syncthreads();

        uint32_t stOff = stage * STGB;
        #pragma unroll
        for (int ks = 0; ks < 2; ks++) {
            uint32_t kByte = (uint32_t)(ks * 16) * 2;
            uint32_t bh[4][2], bl[4][2];
            #pragma unroll
            for (int p = 0; p < 2; p++) {
                uint32_t ad = bBase + stOff + kByte + (uint32_t)(p * 16 * SBQ) * 2;
                ldm4(bh[2*p][0], bh[2*p][1], bh[2*p+1][0], bh[2*p+1][1], ad);
                ldm4(bl[2*p][0], bl[2*p][1], bl[2*p+1][0], bl[2*p+1][1], ad + ARRB);
            }
            #pragma unroll
            for (int mt = 0; mt < 4; mt++) {
                uint32_t ad = aBase + stOff + kByte + (uint32_t)(mt * 16 * SBQ) * 2;
                uint32_t ah[4], al[4];
                ldm4(ah[0], ah[1], ah[2], ah[3], ad);
                ldm4(al[0], al[1], al[2], al[3], ad + ARRB);
                #pragma unroll
                for (int nt = 0; nt < 4; nt++)
                    mma_bf16(acc[mt * 4 + nt], ah, bh[nt]);
                #pragma unroll
                for (int nt = 0; nt < 4; nt++)
                    mma_bf16(acc[mt * 4 + nt], ah, bl[nt]);
                #pragma unroll
                for (int nt = 0; nt < 4; nt++)
                    mma_bf16(acc[mt * 4 + nt], al, bh[nt]);
            }
        }
        __syncthreads();
        stage ^= 1;
    }

    int qr = lane >> 2;
    #pragma unroll
    for (int mt = 0; mt < 4; mt++) {
        #pragma unroll
        for (int nt = 0; nt < 4; nt++) {
            const float* c = acc[mt * 4 + nt];
            int r = m0 + wm * 64 + mt * 16 + qr;
            int cn = n0 + wn * 32 + nt * 8 + (lane & 3) * 2;
            if (cn >= N) continue;
            float bz0 = bz ? bz[cn] : 0.f;
            float bz1 = bz ? bz[cn + 1] : 0.f;
            #pragma unroll
            for (int half = 0; half < 2; half++) {
                int rr = r + half * 8;
                if (rr < M) {
                    float v0 = c[half * 2 + 0] + bz0;
                    float v1 = c[half * 2 + 1] + bz1;
                    if (act == 1) {
                        v0 = 0.5f * v0 * (1.f + erff(v0 * 0.70710678118654752f));
                        v1 = 0.5f * v1 * (1.f + erff(v1 * 0.70710678118654752f));
                    }
                    if (Vth && cn >= 2 * HDIM) {
                        // V portion: write straight into transposed vt[bh][d][key]
                        int cc = cn - 2 * HDIM;
                        int hh_ = cc / HD, d = cc - hh_ * HD;
                        int bb_ = rr >> 9, key = rr & (SQ - 1);
                        size_t bv = ((size_t)(bb_ * NHEAD + hh_) * HD + d) * SQ + key;
                        bf16 h0 = __float2bfloat16_rn(v0);
                        bf16 h1 = __float2bfloat16_rn(v1);
                        Vth[bv]      = h0;
                        Vth[bv + SQ] = h1;
                        Vtl[bv]      = __float2bfloat16_rn(v0 - __bfloat162float(h0));
                        Vtl[bv + SQ] = __float2bfloat16_rn(v1 - __bfloat162float(h1));
                    } else {
                        size_t idx = (size_t)rowmap(rr, mapC) * ldc + cn;
                        if (Cf) { Cf[idx] = v0; Cf[idx + 1] = v1; }
                        if (Ch) {
                            uint32_t H, L;
                            split2(v0, v1, H, L);
                            *(uint32_t*)(Ch + idx) = H;
                            *(uint32_t*)(Cl + idx) = L;
                        }
                    }
                }
            }
        }
    }
}

__global__ __launch_bounds__(256, 2) void gemm_tc(
    int M, int N, int K,
    const bf16* __restrict__ Ah, const bf16* __restrict__ Al, int lda, int mapA,
    const bf16* __restrict__ Wh, const bf16* __restrict__ Wl, int ldw,
    const float* __restrict__ bias,
    float* __restrict__ Cf, bf16* __restrict__ Ch, bf16* __restrict__ Cl,
    int ldc, int mapC, int act,
    bf16* __restrict__ Vth, bf16* __restrict__ Vtl)
{
    gemm_core(M, N, K, Ah, Al, lda, mapA, Wh, Wl, ldw, bias,
              Cf, Ch, Cl, ldc, mapC, act, blockIdx.y * 128, blockIdx.x * 128,
              Vth, Vtl);
}

__global__ __launch_bounds__(256, 2) void gemm_dual(
    int N, int act,
    int M0, int K0, const bf16* __restrict__ Ah0, const bf16* __restrict__ Al0,
    int lda0, int mapA0, const bf16* __restrict__ Wh0, const bf16* __restrict__ Wl0,
    const float* __restrict__ b0,
    int M1, int K1, const bf16* __restrict__ Ah1, const bf16* __restrict__ Al1,
    int lda1, int mapA1, const bf16* __restrict__ Wh1, const bf16* __restrict__ Wl1,
    const float* __restrict__ b1,
    float* __restrict__ Cf, bf16* __restrict__ Ch, bf16* __restrict__ Cl,
    int ldc, int mapC0, int mapC1)
{
    int z = blockIdx.z;
    int M   = z ? M1 : M0;
    int m0  = blockIdx.y * 128;
    if (m0 >= M) return;
    int K   = z ? K1 : K0;
    int lda = z ? lda1 : lda0;
    gemm_core(M, N, K,
              z ? Ah1 : Ah0, z ? Al1 : Al0, lda, z ? mapA1 : mapA0,
              z ? Wh1 : Wh0, z ? Wl1 : Wl0, K,
              z ? b1 : b0,
              Cf, Ch, Cl, ldc, z ? mapC1 : mapC0, act,
              m0, blockIdx.x * 128, nullptr, nullptr);
}

// ================= fused flash attention =================
#define FA_QP 104
#define FA_VPI 136
#define FA_OQH 0
#define FA_OQL 26624
#define FA_OKH 53248
#define FA_OKL 79872
#define FA_OVH 106496
#define FA_OVL 132608
#define FA_OBI 158720
#define FA_SMEM 160768

__global__ __launch_bounds__(256, 1) void flash_attn(
    const bf16* __restrict__ qkvh, const bf16* __restrict__ qkvl,
    const bf16* __restrict__ vth,  const bf16* __restrict__ vtl,
    const float* __restrict__ bias,
    bf16* __restrict__ yh, bf16* __restrict__ yl)
{
    extern __shared__ __align__(128) char fsm[];
    uint32_t s0 = (uint32_t)__cvta_generic_to_shared(fsm);
    int tid = threadIdx.x, wid = tid >> 5, lane = tid & 31;
    int z = blockIdx.z, b = z >> 3, h = z & 7;
    int q0 = blockIdx.x * 128;
    const float scale = 0.10206207261596575f;   // 1/sqrt(96)

    const bf16* gQh = qkvh + (size_t)b * SQ * (3*HDIM) + h * HD;
    const bf16* gQl = qkvl + (size_t)b * SQ * (3*HDIM) + h * HD;
    const bf16* gKh = gQh + HDIM;
    const bf16* gKl = gQl + HDIM;
    const bf16* gVh = vth + (size_t)z * HD * SQ;
    const bf16* gVl = vtl + (size_t)z * HD * SQ;

    if (tid < 128) {
        float4 bv = ((const float4*)(bias + b * SQ))[tid];
        ((float4*)(fsm + FA_OBI))[tid] = bv;
    }
    #pragma unroll
    for (int i = 0; i < 6; i++) {
        int id = tid + i * 256;
        int row = id / 12, cc = id % 12;
        uint32_t dst = s0 + (uint32_t)(row * (FA_QP*2) + cc * 16);
        const bf16* sh_ = gQh + (size_t)(q0 + row) * (3*HDIM) + cc * 8;
        const bf16* sl_ = gQl + (size_t)(q0 + row) * (3*HDIM) + cc * 8;
        cpa16(dst + FA_OQH, sh_);
        cpa16(dst + FA_OQL, sl_);
    }
    asm volatile("cp.async.commit_group;");

    int aLaneRow = (lane & 7) + ((lane >> 3) & 1) * 8;
    int aLaneCol = (lane >> 4) * 8;
    int bLaneRow = (lane & 7) + (lane >> 4) * 8;
    int bLaneCol = ((lane >> 3) & 1) * 8;
    uint32_t aQ = s0 + (uint32_t)((wid * 16 + aLaneRow) * (FA_QP*2) + aLaneCol * 2);
    uint32_t bK = s0 + (uint32_t)(bLaneRow * (FA_QP*2) + bLaneCol * 2);
    uint32_t bV = s0 + (uint32_t)(bLaneRow * (FA_VPI*2) + bLaneCol * 2);

    int g = lane >> 2, t2 = (lane & 3) * 2;
    const float* sbias = (const float*)(fsm + FA_OBI);

    float o[12][4];
    #pragma unroll
    for (int j = 0; j < 12; j++)
        #pragma unroll
        for (int k = 0; k < 4; k++) o[j][k] = 0.f;
    float m0 = -1e30f, m1 = -1e30f, l0 = 0.f, l1 = 0.f;

    for (int kb = 0; kb < 4; kb++) {
        #pragma unroll
        for (int i = 0; i < 6; i++) {
            int id = tid + i * 256;
            int krow = id / 12, kcc = id % 12;
            uint32_t dst = s0 + (uint32_t)(krow * (FA_QP*2) + kcc * 16);
            const bf16* sh_ = gKh + (size_t)(kb * 128 + krow) * (3*HDIM) + kcc * 8;
            const bf16* sl_ = gKl + (size_t)(kb * 128 + krow) * (3*HDIM) + kcc * 8;
            cpa16(dst + FA_OKH, sh_);
            cpa16(dst + FA_OKL, sl_);
            int vrow = id / 16, vcc = id % 16;
            uint32_t vdst = s0 + (uint32_t)(vrow * (FA_VPI*2) + vcc * 16);
            const bf16* vh_ = gVh + (size_t)vrow * SQ + kb * 128 + vcc * 8;
            const bf16* vl_ = gVl + (size_t)vrow * SQ + kb * 128 + vcc * 8;
            cpa16(vdst + FA_OVH, vh_);
            cpa16(vdst + FA_OVL, vl_);
        }
        asm volatile("cp.async.commit_group;");
        asm volatile("cp.async.wait_group 0;");
        __syncthreads();

        float sc[16][4];
        #pragma unroll
        for (int j = 0; j < 16; j++)
            #pragma unroll
            for (int k = 0; k < 4; k++) sc[j][k] = 0.f;
        #pragma unroll
        for (int s = 0; s < 6; s++) {
            uint32_t ah[4], al[4];
            ldm4(ah[0], ah[1], ah[2], ah[3], aQ + FA_OQH + s * 32);
            ldm4(al[0], al[1], al[2], al[3], aQ + FA_OQL + s * 32);
            #pragma unroll
            for (int p = 0; p < 8; p++) {
                uint32_t bh[4], bl[4];
                uint32_t ad = bK + (uint32_t)(p * 16 * (FA_QP*2)) + s * 32;
                ldm4(bh[0], bh[1], bh[2], bh[3], ad + FA_OKH);
                ldm4(bl[0], bl[1], bl[2], bl[3], ad + FA_OKL);
                mma_bf16(sc[2*p],   ah, &bh[0]);
                mma_bf16(sc[2*p+1], ah, &bh[2]);
                mma_bf16(sc[2*p],   ah, &bl[0]);
                mma_bf16(sc[2*p+1], ah, &bl[2]);
                mma_bf16(sc[2*p],   al, &bh[0]);
                mma_bf16(sc[2*p+1], al, &bh[2]);
            }
        }

        float mx0 = -1e30f, mx1 = -1e30f;
        #pragma unroll
        for (int j = 0; j < 16; j++) {
            int col = kb * 128 + j * 8 + t2;
            float bz0 = sbias[col], bz1 = sbias[col + 1];
            sc[j][0] = sc[j][0] * scale + bz0;
            sc[j][1] = sc[j][1] * scale + bz1;
            sc[j][2] = sc[j][2] * scale + bz0;
            sc[j][3] = sc[j][3] * scale + bz1;
            mx0 = fmaxf(mx0, fmaxf(sc[j][0], sc[j][1]));
            mx1 = fmaxf(mx1, fmaxf(sc[j][2], sc[j][3]));
        }
        mx0 = fmaxf(mx0, __shfl_xor_sync(0xffffffffu, mx0, 1));
        mx0 = fmaxf(mx0, __shfl_xor_sync(0xffffffffu, mx0, 2));
        mx1 = fmaxf(mx1, __shfl_xor_sync(0xffffffffu, mx1, 1));
        mx1 = fmaxf(mx1, __shfl_xor_sync(0xffffffffu, mx1, 2));
        float mn0 = fmaxf(m0, mx0), mn1 = fmaxf(m1, mx1);
        float al0 = expf(m0 - mn0), al1 = expf(m1 - mn1);
        m0 = mn0; m1 = mn1;
        float sum0 = 0.f, sum1 = 0.f;
        #pragma unroll
        for (int j = 0; j < 16; j++) {
            sc[j][0] = expf(sc[j][0] - m0);
            sc[j][1] = expf(sc[j][1] - m0);
            sc[j][2] = expf(sc[j][2] - m1);
            sc[j][3] = expf(sc[j][3] - m1);
            sum0 += sc[j][0] + sc[j][1];
            sum1 += sc[j][2] + sc[j][3];
        }
        sum0 += __shfl_xor_sync(0xffffffffu, sum0, 1);
        sum0 += __shfl_xor_sync(0xffffffffu, sum0, 2);
        sum1 += __shfl_xor_sync(0xffffffffu, sum1, 1);
        sum1 += __shfl_xor_sync(0xffffffffu, sum1, 2);
        l0 = l0 * al0 + sum0;
        l1 = l1 * al1 + sum1;
        #pragma unroll
        for (int j = 0; j < 12; j++) {
            o[j][0] *= al0; o[j][1] *= al0; o[j][2] *= al1; o[j][3] *= al1;
        }

        #pragma unroll
        for (int s = 0; s < 8; s++) {
            uint32_t pah[4], pal[4];
            split2(sc[2*s][0],   sc[2*s][1],   pah[0], pal[0]);
            split2(sc[2*s][2],   sc[2*s][3],   pah[1], pal[1]);
            split2(sc[2*s+1][0], sc[2*s+1][1], pah[2], pal[2]);
            split2(sc[2*s+1][2], sc[2*s+1][3], pah[3], pal[3]);
            #pragma unroll
            for (int p = 0; p < 6; p++) {
                uint32_t bh[4], bl[4];
                uint32_t ad = bV + (uint32_t)(p * 16 * (FA_VPI*2)) + s * 32;
                ldm4(bh[0], bh[1], bh[2], bh[3], ad + FA_OVH);
                ldm4(bl[0], bl[1], bl[2], bl[3], ad + FA_OVL);
                mma_bf16(o[2*p],   pah, &bh[0]);
                mma_bf16(o[2*p+1], pah, &bh[2]);
                mma_bf16(o[2*p],   pah, &bl[0]);
                mma_bf16(o[2*p+1], pah, &bl[2]);
                mma_bf16(o[2*p],   pal, &bh[0]);
                mma_bf16(o[2*p+1], pal, &bh[2]);
            }
        }
        __syncthreads();
    }

    float inv0 = 1.f / l0, inv1 = 1.f / l1;
    int r0 = q0 + wid * 16 + g;
    size_t row0 = (size_t)(b * SQ + r0) * HDIM + h * HD;
    size_t row1 = row0 + 8 * HDIM;
    #pragma unroll
    for (int j = 0; j < 12; j++) {
        int d = j * 8 + t2;
        uint32_t H, L;
        split2(o[j][0] * inv0, o[j][1] * inv0, H, L);
        *(uint32_t*)(yh + row0 + d) = H;
        *(uint32_t*)(yl + row0 + d) = L;
        split2(o[j][2] * inv1, o[j][3] * inv1, H, L);
        *(uint32_t*)(yh + row1 + d) = H;
        *(uint32_t*)(yl + row1 + d) = L;
    }
}

// ---------------- residual + LayerNorm, writes fp32 + split-bf16 ----------
__global__ void ln_row(const float* __restrict__ a, const float* __restrict__ res,
                       const float* __restrict__ g1, const float* __restrict__ b1,
                       const float* __restrict__ g2, const float* __restrict__ b2,
                       float* __restrict__ out, bf16* __restrict__ outH,
                       bf16* __restrict__ outL)
{
    __shared__ float sh[8];
    int m = blockIdx.x;
    int s = m & (SQ - 1);
    const float* gg = (s < VP) ? g1 : g2;
    const float* bb = (s < VP) ? b1 : b2;
    const float* ar = a + (size_t)m * HDIM;
    const float* rr = res ? res + (size_t)m * HDIM : nullptr;
    int t = threadIdx.x;  // 256
    float v[3];
    float sum = 0.f;
    #pragma unroll
    for (int i = 0; i < 3; i++) {
        float xv = ar[t + i * 256];
        if (rr) xv += rr[t + i * 256];
        v[i] = xv; sum += xv;
    }
    float mean = blkSum(sum, sh) * (1.f / HDIM);
    float sq = 0.f;
    #pragma unroll
    for (int i = 0; i < 3; i++) { float d = v[i] - mean; sq += d * d; }
    float var = blkSum(sq, sh) * (1.f / HDIM);
    float inv = rsqrtf(var + 1e-5f);
    size_t ob = (size_t)m * HDIM;
    #pragma unroll
    for (int i = 0; i < 3; i++) {
        int c = t + i * 256;
        float o = (v[i] - mean) * inv * gg[c] + bb[c];
        out[ob + c] = o;
        bf16 hi = __float2bfloat16_rn(o);
        outH[ob + c] = hi;
        outL[ob + c] = __float2bfloat16_rn(o - __bfloat162float(hi));
    }
}

// ---------------- key padding bias (mask as 4-byte words) ----------------
__global__ void build_bias(const int* __restrict__ mask, float* __restrict__ bias) {
    int i = blockIdx.x * 256 + threadIdx.x;
    if (i < NB * SQ) {
        int s = i & (SQ - 1);
        float v = 0.f;
        if (s >= VP) {
            int b = i >> 9;
            v = (mask[b * TLN + (s - VP)] != 0) ? 0.f : -1e30f;
        }
        bias[i] = v;
    }
}

// ---------------- mask tail of output ----------------
__global__ void mask_tail(const int* __restrict__ mask, float* __restrict__ out,
                          int out_size) {
    int i = blockIdx.x * 256 + threadIdx.x;
    int n = MROWS * HDIM + i;
    if (i >= NB * SQ || n >= out_size) return;
    int s = i & (SQ - 1);
    int b = i >> 9;
    out[n] = (s < VP) ? 1.f : ((mask[b * TLN + (s - VP)] != 0) ? 1.f : 0.f);
}

// ---------------- host ----------------
static inline void split(const float* src, bf16* h, bf16* l, long long n) {
    int n4 = (int)(n / 4);
    cvt_split<<<(n4 + 255) / 256, 256>>>((const float4*)src, h, l, n4);
}

extern "C" void kernel_launch(void* const* d_in, const int* in_sizes, int n_in,
                              void* d_out, int out_size) {
    (void)in_sizes; (void)n_in;
    static int smem_set = 0;
    if (!smem_set) {
        cudaFuncSetAttribute(gemm_tc,    cudaFuncAttributeMaxDynamicSharedMemorySize, SMEM_TOT);
        cudaFuncSetAttribute(gemm_dual,  cudaFuncAttributeMaxDynamicSharedMemorySize, SMEM_TOT);
        cudaFuncSetAttribute(flash_attn, cudaFuncAttributeMaxDynamicSharedMemorySize, FA_SMEM);
        smem_set = 1;
    }
    const float* vis   = (const float*)d_in[0];
    const float* txt   = (const float*)d_in[1];
    const int*   mask  = (const int*)d_in[2];
    const float* vp_w = (const float*)d_in[3];
    const float* vp_b = (const float*)d_in[4];
    const float* vp_g = (const float*)d_in[5];
    const float* vp_be= (const float*)d_in[6];
    const float* tp_w = (const float*)d_in[7];
    const float* tp_b = (const float*)d_in[8];
    const float* tp_g = (const float*)d_in[9];
    const float* tp_be= (const float*)d_in[10];
    const float* in_w = (const float*)d_in[11];
    const float* in_b = (const float*)d_in[12];
    const float* out_w= (const float*)d_in[13];
    const float* out_b= (const float*)d_in[14];
    const float* ln1g = (const float*)d_in[15];
    const float* ln1b = (const float*)d_in[16];
    const float* vew1 = (const float*)d_in[17];
    const float* veb1 = (const float*)d_in[18];
    const float* vew2 = (const float*)d_in[19];
    const float* veb2 = (const float*)d_in[20];
    const float* lew1 = (const float*)d_in[21];
    const float* leb1 = (const float*)d_in[22];
    const float* lew2 = (const float*)d_in[23];
    const float* leb2 = (const float*)d_in[24];
    const float* ln2g = (const float*)d_in[25];
    const float* ln2b = (const float*)d_in[26];

    float *x, *attn, *ffn, *bias;
    bf16 *wh, *wl, *vish, *visl, *txth, *txtl, *xh, *xl, *qh, *ql;
    bf16 *vth, *vtl, *yh, *yl, *hh, *hl;
    cudaGetSymbolAddress((void**)&x,    g_x);
    cudaGetSymbolAddress((void**)&attn, g_attn);
    cudaGetSymbolAddress((void**)&ffn,  g_ffn);
    cudaGetSymbolAddress((void**)&bias, g_bias);
    cudaGetSymbolAddress((void**)&wh,   g_wh);
    cudaGetSymbolAddress((void**)&wl,   g_wl);
    cudaGetSymbolAddress((void**)&vish, g_vish);
    cudaGetSymbolAddress((void**)&visl, g_visl);
    cudaGetSymbolAddress((void**)&txth, g_txth);
    cudaGetSymbolAddress((void**)&txtl, g_txtl);
    cudaGetSymbolAddress((void**)&xh,   g_xh);
    cudaGetSymbolAddress((void**)&xl,   g_xl);
    cudaGetSymbolAddress((void**)&qh,   g_qkvh);
    cudaGetSymbolAddress((void**)&ql,   g_qkvl);
    cudaGetSymbolAddress((void**)&vth,  g_vth);
    cudaGetSymbolAddress((void**)&vtl,  g_vtl);
    cudaGetSymbolAddress((void**)&yh,   g_yh);
    cudaGetSymbolAddress((void**)&yl,   g_yl);
    cudaGetSymbolAddress((void**)&hh,   g_hh);
    cudaGetSymbolAddress((void**)&hl,   g_hl);

    // ---- prologue ----
    build_bias<<<32, 256>>>(mask, bias);
    split(vis,   vish, visl, (long long)3136 * VD);
    split(txt,   txth, txtl, (long long)5056 * HDIM);
    split(vp_w,  wh + OFF_VPW,  wl + OFF_VPW,  (long long)HDIM * VD);
    split(tp_w,  wh + OFF_TPW,  wl + OFF_TPW,  (long long)HDIM * HDIM);

    // merged input projections (vision z=0, text z=1) -> x (mapped rows)
    gemm_dual<<<dim3(6, 40, 2), 256, SMEM_TOT>>>(HDIM, 0,
        3136, VD,   vish, visl, VD,   0, wh + OFF_VPW, wl + OFF_VPW, vp_b,
        5056, HDIM, txth, txtl, HDIM, 0, wh + OFF_TPW, wl + OFF_TPW, tp_b,
        x, nullptr, nullptr, HDIM, 1, 2);

    split(in_w,  wh + OFF_INW,  wl + OFF_INW,  (long long)NLAYER * 3 * HDIM * HDIM);
    split(out_w, wh + OFF_OUTW, wl + OFF_OUTW, (long long)NLAYER * HDIM * HDIM);
    split(vew1,  wh + OFF_VW1,  wl + OFF_VW1,  (long long)NLAYER * FFD * HDIM);
    split(lew1,  wh + OFF_LW1,  wl + OFF_LW1,  (long long)NLAYER * FFD * HDIM);
    split(vew2,  wh + OFF_VW2,  wl + OFF_VW2,  (long long)NLAYER * HDIM * FFD);
    split(lew2,  wh + OFF_LW2,  wl + OFF_LW2,  (long long)NLAYER * HDIM * FFD);

    ln_row<<<MROWS, 256>>>(x, nullptr, vp_g, vp_be, tp_g, tp_be, x, xh, xl);

    for (int i = 0; i < NLAYER; i++) {
        const bf16* iwh = wh + OFF_INW  + (size_t)i * 3 * HDIM * HDIM;
        const bf16* iwl = wl + OFF_INW  + (size_t)i * 3 * HDIM * HDIM;
        const bf16* owh = wh + OFF_OUTW + (size_t)i * HDIM * HDIM;
        const bf16* owl = wl + OFF_OUTW + (size_t)i * HDIM * HDIM;
        const bf16* v1h = wh + OFF_VW1  + (size_t)i * FFD * HDIM;
        const bf16* v1l = wl + OFF_VW1  + (size_t)i * FFD * HDIM;
        const bf16* l1h = wh + OFF_LW1  + (size_t)i * FFD * HDIM;
        const bf16* l1l = wl + OFF_LW1  + (size_t)i * FFD * HDIM;
        const bf16* v2h = wh + OFF_VW2  + (size_t)i * HDIM * FFD;
        const bf16* v2l = wl + OFF_VW2  + (size_t)i * HDIM * FFD;
        const bf16* l2h = wh + OFF_LW2  + (size_t)i * HDIM * FFD;
        const bf16* l2l = wl + OFF_LW2  + (size_t)i * HDIM * FFD;
        const float* ib  = in_b  + (size_t)i * 3 * HDIM;
        const float* ob  = out_b + (size_t)i * HDIM;
        const float* g1  = ln1g + (size_t)i * HDIM;
        const float* be1 = ln1b + (size_t)i * HDIM;
        const float* g2  = ln2g + (size_t)i * HDIM;
        const float* be2 = ln2b + (size_t)i * HDIM;
        const float* vb1 = veb1 + (size_t)i * FFD;
        const float* vb2 = veb2 + (size_t)i * HDIM;
        const float* lb1 = leb1 + (size_t)i * FFD;
        const float* lb2 = leb2 + (size_t)i * HDIM;

        // QKV projection -> split bf16 (V written transposed in-epilogue)
        gemm_tc<<<dim3(18, 64), 256, SMEM_TOT>>>(MROWS, 3 * HDIM, HDIM,
            xh, xl, HDIM, 0, iwh, iwl, HDIM, ib,
            nullptr, qh, ql, 3 * HDIM, 0, 0, vth, vtl);

        // fused attention: scores + softmax + P·V
        flash_attn<<<dim3(4, 1, NB * NHEAD), 256, FA_SMEM>>>(qh, ql, vth, vtl,
                                                             bias, yh, yl);

        // out projection -> fp32
        gemm_tc<<<dim3(6, 64), 256, SMEM_TOT>>>(MROWS, HDIM, HDIM,
            yh, yl, HDIM, 0, owh, owl, HDIM, ob,
            attn, nullptr, nullptr, HDIM, 0, 0, nullptr, nullptr);

        ln_row<<<MROWS, 256>>>(x, attn, g1, be1, g1, be1, x, xh, xl);

        // dual-expert FFN (GELU) merged launches
        gemm_dual<<<dim3(24, 40, 2), 256, SMEM_TOT>>>(FFD, 1,
            3136, HDIM, xh, xl, HDIM, 1, v1h, v1l, vb1,
            5056, HDIM, xh, xl, HDIM, 2, l1h, l1l, lb1,
            nullptr, hh, hl, FFD, 1, 2);
        gemm_dual<<<dim3(6, 40, 2), 256, SMEM_TOT>>>(HDIM, 0,
            3136, FFD, hh, hl, FFD, 1, v2h, v2l, vb2,
            5056, FFD, hh, hl, FFD, 2, l2h, l2l, lb2,
            ffn, nullptr, nullptr, HDIM, 1, 2);

        // final layer LN writes straight into d_out; others into x
        float* lnOut = (i == NLAYER - 1) ? (float*)d_out : x;
        ln_row<<<MROWS, 256>>>(x, ffn, g2, be2, g2, be2, lnOut, xh, xl);
    }

    mask_tail<<<32, 256>>>(mask, (float*)d_out, out_size);
}

// round 17
// speedup vs baseline: 1.1799x; 1.0080x over previous
#include <cuda_runtime.h>
#include <cuda_bf16.h>
#include <math.h>
#include <stdint.h>

#define VP 196
#define TLN 316
#define SQ 512
#define VD 1024
#define HDIM 768
#define NHEAD 8
#define HD 96
#define FFD 3072
#define NLAYER 6
#define NB 16
#define MROWS (NB*SQ)   /* 8192 */

typedef __nv_bfloat16 bf16;

// ---------------- weight split buffers (hi/lo bf16), one big arena ----------
#define OFF_VPW  0
#define OFF_TPW  786432
#define OFF_INW  1376256
#define OFF_OUTW 11993088
#define OFF_VW1  15532032
#define OFF_LW1  29687808
#define OFF_VW2  43843584
#define OFF_LW2  57999360
#define W_TOTAL  72155136

__device__ __align__(256) bf16 g_wh[W_TOTAL];
__device__ __align__(256) bf16 g_wl[W_TOTAL];

// ---------------- activation scratch ----------------
__device__ __align__(256) float g_x[MROWS*HDIM];
__device__ __align__(256) float g_attn[MROWS*HDIM];
__device__ __align__(256) float g_ffn[MROWS*HDIM];
__device__ __align__(256) float g_bias[NB*SQ];

__device__ __align__(256) bf16 g_vish[3136*VD],  g_visl[3136*VD];
__device__ __align__(256) bf16 g_txth[5056*HDIM], g_txtl[5056*HDIM];
__device__ __align__(256) bf16 g_xh[MROWS*HDIM],  g_xl[MROWS*HDIM];
__device__ __align__(256) bf16 g_qkvh[MROWS*3*HDIM], g_qkvl[MROWS*3*HDIM];
__device__ __align__(256) bf16 g_yh[MROWS*HDIM],  g_yl[MROWS*HDIM];
__device__ __align__(256) bf16 g_hh[MROWS*FFD],   g_hl[MROWS*FFD];

// ---------------- helpers ----------------
__device__ __forceinline__ int rowmap(int i, int mode) {
    if (mode == 1) { int b = i / VP;  return b * SQ + (i - b * VP); }
    if (mode == 2) { int b = i / TLN; return b * SQ + VP + (i - b * TLN); }
    return i;
}

__device__ __forceinline__ float blkSum(float v, float* sh) {
    int lane = threadIdx.x & 31, w = threadIdx.x >> 5, nw = blockDim.x >> 5;
    #pragma unroll
    for (int o = 16; o > 0; o >>= 1) v += __shfl_xor_sync(0xffffffffu, v, o);
    if (lane == 0) sh[w] = v;
    __syncthreads();
    v = (threadIdx.x < nw) ? sh[threadIdx.x] : 0.f;
    if (w == 0) {
        #pragma unroll
        for (int o = 4; o > 0; o >>= 1) v += __shfl_xor_sync(0xffffffffu, v, o);
        if (lane == 0) sh[0] = v;
    }
    __syncthreads();
    v = sh[0];
    __syncthreads();
    return v;
}

// ---------------- fp32 -> bf16 hi/lo split (vectorized) ----------------
__global__ void cvt_split(const float4* __restrict__ src, bf16* __restrict__ H,
                          bf16* __restrict__ L, int n4) {
    int i = blockIdx.x * 256 + threadIdx.x;
    if (i >= n4) return;
    float4 v = src[i];
    bf16 h0 = __float2bfloat16_rn(v.x), h1 = __float2bfloat16_rn(v.y);
    bf16 h2 = __float2bfloat16_rn(v.z), h3 = __float2bfloat16_rn(v.w);
    *(__nv_bfloat162*)(H + 4*i)     = __halves2bfloat162(h0, h1);
    *(__nv_bfloat162*)(H + 4*i + 2) = __halves2bfloat162(h2, h3);
    bf16 l0 = __float2bfloat16_rn(v.x - __bfloat162float(h0));
    bf16 l1 = __float2bfloat16_rn(v.y - __bfloat162float(h1));
    bf16 l2 = __float2bfloat16_rn(v.z - __bfloat162float(h2));
    bf16 l3 = __float2bfloat16_rn(v.w - __bfloat162float(h3));
    *(__nv_bfloat162*)(L + 4*i)     = __halves2bfloat162(l0, l1);
    *(__nv_bfloat162*)(L + 4*i + 2) = __halves2bfloat162(l2, l3);
}

// ================= shared asm wrappers =================
__device__ __forceinline__ void mma_bf16(float* c, const uint32_t* a, const uint32_t* b) {
    asm volatile(
        "mma.sync.aligned.m16n8k16.row.col.f32.bf16.bf16.f32 "
        "{%0,%1,%2,%3}, {%4,%5,%6,%7}, {%8,%9}, {%0,%1,%2,%3};"
        : "+f"(c[0]), "+f"(c[1]), "+f"(c[2]), "+f"(c[3])
        : "r"(a[0]), "r"(a[1]), "r"(a[2]), "r"(a[3]), "r"(b[0]), "r"(b[1]));
}

__device__ __forceinline__ void cpa16(uint32_t saddr, const void* gptr) {
    asm volatile("cp.async.cg.shared.global [%0], [%1], 16;" :: "r"(saddr), "l"(gptr));
}

__device__ __forceinline__ void ldm4(uint32_t& r0, uint32_t& r1, uint32_t& r2,
                                     uint32_t& r3, uint32_t addr) {
    asm volatile("ldmatrix.sync.aligned.m8n8.x4.shared.b16 {%0,%1,%2,%3}, [%4];"
                 : "=r"(r0), "=r"(r1), "=r"(r2), "=r"(r3) : "r"(addr));
}

__device__ __forceinline__ void ldm4t(uint32_t& r0, uint32_t& r1, uint32_t& r2,
                                      uint32_t& r3, uint32_t addr) {
    asm volatile("ldmatrix.sync.aligned.m8n8.x4.trans.shared.b16 {%0,%1,%2,%3}, [%4];"
                 : "=r"(r0), "=r"(r1), "=r"(r2), "=r"(r3) : "r"(addr));
}

__device__ __forceinline__ void split2(float x, float y, uint32_t& H, uint32_t& L) {
    bf16 hx = __float2bfloat16_rn(x), hy = __float2bfloat16_rn(y);
    __nv_bfloat162 h2 = __halves2bfloat162(hx, hy);
    H = *(uint32_t*)&h2;
    __nv_bfloat162 l2 = __halves2bfloat162(
        __float2bfloat16_rn(x - __bfloat162float(hx)),
        __float2bfloat16_rn(y - __bfloat162float(hy)));
    L = *(uint32_t*)&l2;
}

// ================= split-bf16 GEMM core: 128x128 tile, 2 CTA/SM =================
#define SBQ 40
#define ARRB (128*SBQ*2)
#define STGB (4*ARRB)
#define SMEM_TOT (2*STGB)

__device__ __forceinline__ void gemm_core(
    int M, int N, int K,
    const bf16* __restrict__ Ah, const bf16* __restrict__ Al, int lda, int mapA,
    const bf16* __restrict__ Wh, const bf16* __restrict__ Wl, int ldw,
    const float* __restrict__ bz,
    float* __restrict__ Cf, bf16* __restrict__ Ch, bf16* __restrict__ Cl,
    int ldc, int mapC, int act, int m0, int n0)
{
    extern __shared__ __align__(128) bf16 smem[];
    int tid = threadIdx.x;
    int wid = tid >> 5, lane = tid & 31;
    int wm = wid >> 2, wn = wid & 3;

    int lrow = tid & 127;
    int c0 = (tid >> 7) * 16;
    int arow = m0 + lrow; if (arow >= M) arow = M - 1;
    int wrow = n0 + lrow; if (wrow >= N) wrow = N - 1;
    const bf16* gA_h = Ah + (size_t)rowmap(arow, mapA) * lda + c0;
    const bf16* gA_l = Al + (size_t)rowmap(arow, mapA) * lda + c0;
    const bf16* gW_h = Wh + (size_t)wrow * ldw + c0;
    const bf16* gW_l = Wl + (size_t)wrow * ldw + c0;
    uint32_t s0 = (uint32_t)__cvta_generic_to_shared(smem);
    uint32_t sb = (uint32_t)(lrow * SBQ + c0) * 2;

    float acc[16][4];
    #pragma unroll
    for (int i = 0; i < 16; i++)
        #pragma unroll
        for (int j = 0; j < 4; j++) acc[i][j] = 0.f;

    int aLaneRow = (lane & 7) + ((lane >> 3) & 1) * 8;
    int aLaneCol = (lane >> 4) * 8;
    int bLaneRow = (lane & 7) + (lane >> 4) * 8;
    int bLaneCol = ((lane >> 3) & 1) * 8;
    uint32_t aBase = s0 + (uint32_t)((wm * 64 + aLaneRow) * SBQ + aLaneCol) * 2;
    uint32_t bBase = s0 + 2 * ARRB + (uint32_t)((wn * 32 + bLaneRow) * SBQ + bLaneCol) * 2;

    #pragma unroll
    for (int ar = 0; ar < 4; ar++) {
        const bf16* g = (ar == 0) ? gA_h : (ar == 1) ? gA_l : (ar == 2) ? gW_h : gW_l;
        cpa16(s0 + ar * ARRB + sb,      g);
        cpa16(s0 + ar * ARRB + sb + 16, g + 8);
    }
    asm volatile("cp.async.commit_group;");

    int stage = 0;
    for (int k0 = 0; k0 < K; k0 += 32) {
        bool more = (k0 + 32) < K;
        if (more) {
            uint32_t sn = s0 + (stage ^ 1) * STGB;
            #pragma unroll
            for (int ar = 0; ar < 4; ar++) {
                const bf16* g = ((ar == 0) ? gA_h : (ar == 1) ? gA_l :
                                 (ar == 2) ? gW_h : gW_l) + k0 + 32;
                cpa16(sn + ar * ARRB + sb,      g);
                cpa16(sn + ar * ARRB + sb + 16, g + 8);
            }
            asm volatile("cp.async.commit_group;");
            asm volatile("cp.async.wait_group 1;");
        } else {
            asm volatile("cp.async.wait_group 0;");
        }
        __syncthreads();

        uint32_t stOff = stage * STGB;
        #pragma unroll
        for (int ks = 0; ks < 2; ks++) {
            uint32_t kByte = (uint32_t)(ks * 16) * 2;
            uint32_t bh[4][2], bl[4][2];
            #pragma unroll
            for (int p = 0; p < 2; p++) {
                uint32_t ad = bBase + stOff + kByte + (uint32_t)(p * 16 * SBQ) * 2;
                ldm4(bh[2*p][0], bh[2*p][1], bh[2*p+1][0], bh[2*p+1][1], ad);
                ldm4(bl[2*p][0], bl[2*p][1], bl[2*p+1][0], bl[2*p+1][1], ad + ARRB);
            }
            #pragma unroll
            for (int mt = 0; mt < 4; mt++) {
                uint32_t ad = aBase + stOff + kByte + (uint32_t)(mt * 16 * SBQ) * 2;
                uint32_t ah[4], al[4];
                ldm4(ah[0], ah[1], ah[2], ah[3], ad);
                ldm4(al[0], al[1], al[2], al[3], ad + ARRB);
                #pragma unroll
                for (int nt = 0; nt < 4; nt++)
                    mma_bf16(acc[mt * 4 + nt], ah, bh[nt]);
                #pragma unroll
                for (int nt = 0; nt < 4; nt++)
                    mma_bf16(acc[mt * 4 + nt], ah, bl[nt]);
                #pragma unroll
                for (int nt = 0; nt < 4; nt++)
                    mma_bf16(acc[mt * 4 + nt], al, bh[nt]);
            }
        }
        __syncthreads();
        stage ^= 1;
    }

    int qr = lane >> 2;
    #pragma unroll
    for (int mt = 0; mt < 4; mt++) {
        #pragma unroll
        for (int nt = 0; nt < 4; nt++) {
            const float* c = acc[mt * 4 + nt];
            int r = m0 + wm * 64 + mt * 16 + qr;
            int cn = n0 + wn * 32 + nt * 8 + (lane & 3) * 2;
            if (cn >= N) continue;
            float bz0 = bz ? bz[cn] : 0.f;
            float bz1 = bz ? bz[cn + 1] : 0.f;
            #pragma unroll
            for (int half = 0; half < 2; half++) {
                int rr = r + half * 8;
                if (rr < M) {
                    float v0 = c[half * 2 + 0] + bz0;
                    float v1 = c[half * 2 + 1] + bz1;
                    if (act == 1) {
                        v0 = 0.5f * v0 * (1.f + erff(v0 * 0.70710678118654752f));
                        v1 = 0.5f * v1 * (1.f + erff(v1 * 0.70710678118654752f));
                    }
                    size_t idx = (size_t)rowmap(rr, mapC) * ldc + cn;
                    if (Cf) { Cf[idx] = v0; Cf[idx + 1] = v1; }
                    if (Ch) {
                        uint32_t H, L;
                        split2(v0, v1, H, L);
                        *(uint32_t*)(Ch + idx) = H;
                        *(uint32_t*)(Cl + idx) = L;
                    }
                }
            }
        }
    }
}

__global__ __launch_bounds__(256, 2) void gemm_tc(
    int M, int N, int K,
    const bf16* __restrict__ Ah, const bf16* __restrict__ Al, int lda, int mapA,
    const bf16* __restrict__ Wh, const bf16* __restrict__ Wl, int ldw,
    const float* __restrict__ bias,
    float* __restrict__ Cf, bf16* __restrict__ Ch, bf16* __restrict__ Cl,
    int ldc, int mapC, int act)
{
    gemm_core(M, N, K, Ah, Al, lda, mapA, Wh, Wl, ldw, bias,
              Cf, Ch, Cl, ldc, mapC, act, blockIdx.y * 128, blockIdx.x * 128);
}

__global__ __launch_bounds__(256, 2) void gemm_dual(
    int N, int act,
    int M0, int K0, const bf16* __restrict__ Ah0, const bf16* __restrict__ Al0,
    int lda0, int mapA0, const bf16* __restrict__ Wh0, const bf16* __restrict__ Wl0,
    const float* __restrict__ b0,
    int M1, int K1, const bf16* __restrict__ Ah1, const bf16* __restrict__ Al1,
    int lda1, int mapA1, const bf16* __restrict__ Wh1, const bf16* __restrict__ Wl1,
    const float* __restrict__ b1,
    float* __restrict__ Cf, bf16* __restrict__ Ch, bf16* __restrict__ Cl,
    int ldc, int mapC0, int mapC1)
{
    int z = blockIdx.z;
    int M   = z ? M1 : M0;
    int m0  = blockIdx.y * 128;
    if (m0 >= M) return;
    int K   = z ? K1 : K0;
    int lda = z ? lda1 : lda0;
    gemm_core(M, N, K,
              z ? Ah1 : Ah0, z ? Al1 : Al0, lda, z ? mapA1 : mapA0,
              z ? Wh1 : Wh0, z ? Wl1 : Wl0, K,
              z ? b1 : b0,
              Cf, Ch, Cl, ldc, z ? mapC1 : mapC0, act,
              m0, blockIdx.x * 128);
}

// ================= fused flash attention =================
// Q/K/V all staged [rows=128][cols=96] at pitch FA_QP; V fragments via ldmatrix.trans.
#define FA_QP 104
#define FA_OQH 0
#define FA_OQL 26624
#define FA_OKH 53248
#define FA_OKL 79872
#define FA_OVH 106496
#define FA_OVL 133120
#define FA_OBI 159744
#define FA_SMEM 161792

__global__ __launch_bounds__(256, 1) void flash_attn(
    const bf16* __restrict__ qkvh, const bf16* __restrict__ qkvl,
    const float* __restrict__ bias,
    bf16* __restrict__ yh, bf16* __restrict__ yl)
{
    extern __shared__ __align__(128) char fsm[];
    uint32_t s0 = (uint32_t)__cvta_generic_to_shared(fsm);
    int tid = threadIdx.x, wid = tid >> 5, lane = tid & 31;
    int z = blockIdx.z, b = z >> 3, h = z & 7;
    int q0 = blockIdx.x * 128;
    const float scale = 0.10206207261596575f;   // 1/sqrt(96)

    const bf16* gQh = qkvh + (size_t)b * SQ * (3*HDIM) + h * HD;
    const bf16* gQl = qkvl + (size_t)b * SQ * (3*HDIM) + h * HD;
    const bf16* gKh = gQh + HDIM;
    const bf16* gKl = gQl + HDIM;
    const bf16* gVh = gQh + 2 * HDIM;
    const bf16* gVl = gQl + 2 * HDIM;

    if (tid < 128) {
        float4 bv = ((const float4*)(bias + b * SQ))[tid];
        ((float4*)(fsm + FA_OBI))[tid] = bv;
    }
    #pragma unroll
    for (int i = 0; i < 6; i++) {
        int id = tid + i * 256;
        int row = id / 12, cc = id % 12;
        uint32_t dst = s0 + (uint32_t)(row * (FA_QP*2) + cc * 16);
        const bf16* sh_ = gQh + (size_t)(q0 + row) * (3*HDIM) + cc * 8;
        const bf16* sl_ = gQl + (size_t)(q0 + row) * (3*HDIM) + cc * 8;
        cpa16(dst + FA_OQH, sh_);
        cpa16(dst + FA_OQL, sl_);
    }
    asm volatile("cp.async.commit_group;");

    int aLaneRow = (lane & 7) + ((lane >> 3) & 1) * 8;
    int aLaneCol = (lane >> 4) * 8;
    int bLaneRow = (lane & 7) + (lane >> 4) * 8;
    int bLaneCol = ((lane >> 3) & 1) * 8;
    // trans addressing for V (rows = key, cols = d)
    int vLaneRow = (lane & 7) + ((lane >> 3) & 1) * 8;
    int vLaneCol = (lane >> 4) * 8;
    uint32_t aQ = s0 + (uint32_t)((wid * 16 + aLaneRow) * (FA_QP*2) + aLaneCol * 2);
    uint32_t bK = s0 + (uint32_t)(bLaneRow * (FA_QP*2) + bLaneCol * 2);
    uint32_t bV = s0 + (uint32_t)(vLaneRow * (FA_QP*2) + vLaneCol * 2);

    int g = lane >> 2, t2 = (lane & 3) * 2;
    const float* sbias = (const float*)(fsm + FA_OBI);

    float o[12][4];
    #pragma unroll
    for (int j = 0; j < 12; j++)
        #pragma unroll
        for (int k = 0; k < 4; k++) o[j][k] = 0.f;
    float m0 = -1e30f, m1 = -1e30f, l0 = 0.f, l1 = 0.f;

    for (int kb = 0; kb < 4; kb++) {
        // stage K and V blocks (both [128 key rows][96 cols], pitch FA_QP)
        #pragma unroll
        for (int i = 0; i < 6; i++) {
            int id = tid + i * 256;
            int krow = id / 12, kcc = id % 12;
            uint32_t off = (uint32_t)(krow * (FA_QP*2) + kcc * 16);
            size_t src = (size_t)(kb * 128 + krow) * (3*HDIM) + kcc * 8;
            cpa16(s0 + FA_OKH + off, gKh + src);
            cpa16(s0 + FA_OKL + off, gKl + src);
            cpa16(s0 + FA_OVH + off, gVh + src);
            cpa16(s0 + FA_OVL + off, gVl + src);
        }
        asm volatile("cp.async.commit_group;");
        asm volatile("cp.async.wait_group 0;");
        __syncthreads();

        float sc[16][4];
        #pragma unroll
        for (int j = 0; j < 16; j++)
            #pragma unroll
            for (int k = 0; k < 4; k++) sc[j][k] = 0.f;
        #pragma unroll
        for (int s = 0; s < 6; s++) {
            uint32_t ah[4], al[4];
            ldm4(ah[0], ah[1], ah[2], ah[3], aQ + FA_OQH + s * 32);
            ldm4(al[0], al[1], al[2], al[3], aQ + FA_OQL + s * 32);
            #pragma unroll
            for (int p = 0; p < 8; p++) {
                uint32_t bh[4], bl[4];
                uint32_t ad = bK + (uint32_t)(p * 16 * (FA_QP*2)) + s * 32;
                ldm4(bh[0], bh[1], bh[2], bh[3], ad + FA_OKH);
                ldm4(bl[0], bl[1], bl[2], bl[3], ad + FA_OKL);
                mma_bf16(sc[2*p],   ah, &bh[0]);
                mma_bf16(sc[2*p+1], ah, &bh[2]);
                mma_bf16(sc[2*p],   ah, &bl[0]);
                mma_bf16(sc[2*p+1], ah, &bl[2]);
                mma_bf16(sc[2*p],   al, &bh[0]);
                mma_bf16(sc[2*p+1], al, &bh[2]);
            }
        }

        float mx0 = -1e30f, mx1 = -1e30f;
        #pragma unroll
        for (int j = 0; j < 16; j++) {
            int col = kb * 128 + j * 8 + t2;
            float bz0 = sbias[col], bz1 = sbias[col + 1];
            sc[j][0] = sc[j][0] * scale + bz0;
            sc[j][1] = sc[j][1] * scale + bz1;
            sc[j][2] = sc[j][2] * scale + bz0;
            sc[j][3] = sc[j][3] * scale + bz1;
            mx0 = fmaxf(mx0, fmaxf(sc[j][0], sc[j][1]));
            mx1 = fmaxf(mx1, fmaxf(sc[j][2], sc[j][3]));
        }
        mx0 = fmaxf(mx0, __shfl_xor_sync(0xffffffffu, mx0, 1));
        mx0 = fmaxf(mx0, __shfl_xor_sync(0xffffffffu, mx0, 2));
        mx1 = fmaxf(mx1, __shfl_xor_sync(0xffffffffu, mx1, 1));
        mx1 = fmaxf(mx1, __shfl_xor_sync(0xffffffffu, mx1, 2));
        float mn0 = fmaxf(m0, mx0), mn1 = fmaxf(m1, mx1);
        float al0 = expf(m0 - mn0), al1 = expf(m1 - mn1);
        m0 = mn0; m1 = mn1;
        float sum0 = 0.f, sum1 = 0.f;
        #pragma unroll
        for (int j = 0; j < 16; j++) {
            sc[j][0] = expf(sc[j][0] - m0);
            sc[j][1] = expf(sc[j][1] - m0);
            sc[j][2] = expf(sc[j][2] - m1);
            sc[j][3] = expf(sc[j][3] - m1);
            sum0 += sc[j][0] + sc[j][1];
            sum1 += sc[j][2] + sc[j][3];
        }
        sum0 += __shfl_xor_sync(0xffffffffu, sum0, 1);
        sum0 += __shfl_xor_sync(0xffffffffu, sum0, 2);
        sum1 += __shfl_xor_sync(0xffffffffu, sum1, 1);
        sum1 += __shfl_xor_sync(0xffffffffu, sum1, 2);
        l0 = l0 * al0 + sum0;
        l1 = l1 * al1 + sum1;
        #pragma unroll
        for (int j = 0; j < 12; j++) {
            o[j][0] *= al0; o[j][1] *= al0; o[j][2] *= al1; o[j][3] *= al1;
        }

        // O += P·V : V fragments via ldmatrix.trans from [key][d] layout
        #pragma unroll
        for (int s = 0; s < 8; s++) {
            uint32_t pah[4], pal[4];
            split2(sc[2*s][0],   sc[2*s][1],   pah[0], pal[0]);
            split2(sc[2*s][2],   sc[2*s][3],   pah[1], pal[1]);
            split2(sc[2*s+1][0], sc[2*s+1][1], pah[2], pal[2]);
            split2(sc[2*s+1][2], sc[2*s+1][3], pah[3], pal[3]);
            #pragma unroll
            for (int p = 0; p < 6; p++) {
                uint32_t bh[4], bl[4];
                uint32_t ad = bV + (uint32_t)(s * 16 * (FA_QP*2)) + (uint32_t)(p * 16) * 2;
                ldm4t(bh[0], bh[1], bh[2], bh[3], ad + FA_OVH);
                ldm4t(bl[0], bl[1], bl[2], bl[3], ad + FA_OVL);
                mma_bf16(o[2*p],   pah, &bh[0]);
                mma_bf16(o[2*p+1], pah, &bh[2]);
                mma_bf16(o[2*p],   pah, &bl[0]);
                mma_bf16(o[2*p+1], pah, &bl[2]);
                mma_bf16(o[2*p],   pal, &bh[0]);
                mma_bf16(o[2*p+1], pal, &bh[2]);
            }
        }
        __syncthreads();
    }

    float inv0 = 1.f / l0, inv1 = 1.f / l1;
    int r0 = q0 + wid * 16 + g;
    size_t row0 = (size_t)(b * SQ + r0) * HDIM + h * HD;
    size_t row1 = row0 + 8 * HDIM;
    #pragma unroll
    for (int j = 0; j < 12; j++) {
        int d = j * 8 + t2;
        uint32_t H, L;
        split2(o[j][0] * inv0, o[j][1] * inv0, H, L);
        *(uint32_t*)(yh + row0 + d) = H;
        *(uint32_t*)(yl + row0 + d) = L;
        split2(o[j][2] * inv1, o[j][3] * inv1, H, L);
        *(uint32_t*)(yh + row1 + d) = H;
        *(uint32_t*)(yl + row1 + d) = L;
    }
}

// ---------------- residual + LayerNorm, writes fp32 + split-bf16 ----------
__global__ void ln_row(const float* __restrict__ a, const float* __restrict__ res,
                       const float* __restrict__ g1, const float* __restrict__ b1,
                       const float* __restrict__ g2, const float* __restrict__ b2,
                       float* __restrict__ out, bf16* __restrict__ outH,
                       bf16* __restrict__ outL)
{
    __shared__ float sh[8];
    int m = blockIdx.x;
    int s = m & (SQ - 1);
    const float* gg = (s < VP) ? g1 : g2;
    const float* bb = (s < VP) ? b1 : b2;
    const float* ar = a + (size_t)m * HDIM;
    const float* rr = res ? res + (size_t)m * HDIM : nullptr;
    int t = threadIdx.x;  // 256
    float v[3];
    float sum = 0.f;
    #pragma unroll
    for (int i = 0; i < 3; i++) {
        float xv = ar[t + i * 256];
        if (rr) xv += rr[t + i * 256];
        v[i] = xv; sum += xv;
    }
    float mean = blkSum(sum, sh) * (1.f / HDIM);
    float sq = 0.f;
    #pragma unroll
    for (int i = 0; i < 3; i++) { float d = v[i] - mean; sq += d * d; }
    float var = blkSum(sq, sh) * (1.f / HDIM);
    float inv = rsqrtf(var + 1e-5f);
    size_t ob = (size_t)m * HDIM;
    #pragma unroll
    for (int i = 0; i < 3; i++) {
        int c = t + i * 256;
        float o = (v[i] - mean) * inv * gg[c] + bb[c];
        out[ob + c] = o;
        bf16 hi = __float2bfloat16_rn(o);
        outH[ob + c] = hi;
        outL[ob + c] = __float2bfloat16_rn(o - __bfloat162float(hi));
    }
}

// ---------------- key padding bias (mask as 4-byte words) ----------------
__global__ void build_bias(const int* __restrict__ mask, float* __restrict__ bias) {
    int i = blockIdx.x * 256 + threadIdx.x;
    if (i < NB * SQ) {
        int s = i & (SQ - 1);
        float v = 0.f;
        if (s >= VP) {
            int b = i >> 9;
            v = (mask[b * TLN + (s - VP)] != 0) ? 0.f : -1e30f;
        }
        bias[i] = v;
    }
}

// ---------------- mask tail of output ----------------
__global__ void mask_tail(const int* __restrict__ mask, float* __restrict__ out,
                          int out_size) {
    int i = blockIdx.x * 256 + threadIdx.x;
    int n = MROWS * HDIM + i;
    if (i >= NB * SQ || n >= out_size) return;
    int s = i & (SQ - 1);
    int b = i >> 9;
    out[n] = (s < VP) ? 1.f : ((mask[b * TLN + (s - VP)] != 0) ? 1.f : 0.f);
}

// ---------------- host ----------------
static inline void split(const float* src, bf16* h, bf16* l, long long n) {
    int n4 = (int)(n / 4);
    cvt_split<<<(n4 + 255) / 256, 256>>>((const float4*)src, h, l, n4);
}

extern "C" void kernel_launch(void* const* d_in, const int* in_sizes, int n_in,
                              void* d_out, int out_size) {
    (void)in_sizes; (void)n_in;
    static int smem_set = 0;
    if (!smem_set) {
        cudaFuncSetAttribute(gemm_tc,    cudaFuncAttributeMaxDynamicSharedMemorySize, SMEM_TOT);
        cudaFuncSetAttribute(gemm_dual,  cudaFuncAttributeMaxDynamicSharedMemorySize, SMEM_TOT);
        cudaFuncSetAttribute(flash_attn, cudaFuncAttributeMaxDynamicSharedMemorySize, FA_SMEM);
        smem_set = 1;
    }
    const float* vis   = (const float*)d_in[0];
    const float* txt   = (const float*)d_in[1];
    const int*   mask  = (const int*)d_in[2];
    const float* vp_w = (const float*)d_in[3];
    const float* vp_b = (const float*)d_in[4];
    const float* vp_g = (const float*)d_in[5];
    const float* vp_be= (const float*)d_in[6];
    const float* tp_w = (const float*)d_in[7];
    const float* tp_b = (const float*)d_in[8];
    const float* tp_g = (const float*)d_in[9];
    const float* tp_be= (const float*)d_in[10];
    const float* in_w = (const float*)d_in[11];
    const float* in_b = (const float*)d_in[12];
    const float* out_w= (const float*)d_in[13];
    const float* out_b= (const float*)d_in[14];
    const float* ln1g = (const float*)d_in[15];
    const float* ln1b = (const float*)d_in[16];
    const float* vew1 = (const float*)d_in[17];
    const float* veb1 = (const float*)d_in[18];
    const float* vew2 = (const float*)d_in[19];
    const float* veb2 = (const float*)d_in[20];
    const float* lew1 = (const float*)d_in[21];
    const float* leb1 = (const float*)d_in[22];
    const float* lew2 = (const float*)d_in[23];
    const float* leb2 = (const float*)d_in[24];
    const float* ln2g = (const float*)d_in[25];
    const float* ln2b = (const float*)d_in[26];

    float *x, *attn, *ffn, *bias;
    bf16 *wh, *wl, *vish, *visl, *txth, *txtl, *xh, *xl, *qh, *ql;
    bf16 *yh, *yl, *hh, *hl;
    cudaGetSymbolAddress((void**)&x,    g_x);
    cudaGetSymbolAddress((void**)&attn, g_attn);
    cudaGetSymbolAddress((void**)&ffn,  g_ffn);
    cudaGetSymbolAddress((void**)&bias, g_bias);
    cudaGetSymbolAddress((void**)&wh,   g_wh);
    cudaGetSymbolAddress((void**)&wl,   g_wl);
    cudaGetSymbolAddress((void**)&vish, g_vish);
    cudaGetSymbolAddress((void**)&visl, g_visl);
    cudaGetSymbolAddress((void**)&txth, g_txth);
    cudaGetSymbolAddress((void**)&txtl, g_txtl);
    cudaGetSymbolAddress((void**)&xh,   g_xh);
    cudaGetSymbolAddress((void**)&xl,   g_xl);
    cudaGetSymbolAddress((void**)&qh,   g_qkvh);
    cudaGetSymbolAddress((void**)&ql,   g_qkvl);
    cudaGetSymbolAddress((void**)&yh,   g_yh);
    cudaGetSymbolAddress((void**)&yl,   g_yl);
    cudaGetSymbolAddress((void**)&hh,   g_hh);
    cudaGetSymbolAddress((void**)&hl,   g_hl);

    // ---- prologue ----
    build_bias<<<32, 256>>>(mask, bias);
    split(vis,   vish, visl, (long long)3136 * VD);
    split(txt,   txth, txtl, (long long)5056 * HDIM);
    split(vp_w,  wh + OFF_VPW,  wl + OFF_VPW,  (long long)HDIM * VD);
    split(tp_w,  wh + OFF_TPW,  wl + OFF_TPW,  (long long)HDIM * HDIM);

    // merged input projections (vision z=0, text z=1) -> x (mapped rows)
    gemm_dual<<<dim3(6, 40, 2), 256, SMEM_TOT>>>(HDIM, 0,
        3136, VD,   vish, visl, VD,   0, wh + OFF_VPW, wl + OFF_VPW, vp_b,
        5056, HDIM, txth, txtl, HDIM, 0, wh + OFF_TPW, wl + OFF_TPW, tp_b,
        x, nullptr, nullptr, HDIM, 1, 2);

    split(in_w,  wh + OFF_INW,  wl + OFF_INW,  (long long)NLAYER * 3 * HDIM * HDIM);
    split(out_w, wh + OFF_OUTW, wl + OFF_OUTW, (long long)NLAYER * HDIM * HDIM);
    split(vew1,  wh + OFF_VW1,  wl + OFF_VW1,  (long long)NLAYER * FFD * HDIM);
    split(lew1,  wh + OFF_LW1,  wl + OFF_LW1,  (long long)NLAYER * FFD * HDIM);
    split(vew2,  wh + OFF_VW2,  wl + OFF_VW2,  (long long)NLAYER * HDIM * FFD);
    split(lew2,  wh + OFF_LW2,  wl + OFF_LW2,  (long long)NLAYER * HDIM * FFD);

    ln_row<<<MROWS, 256>>>(x, nullptr, vp_g, vp_be, tp_g, tp_be, x, xh, xl);

    for (int i = 0; i < NLAYER; i++) {
        const bf16* iwh = wh + OFF_INW  + (size_t)i * 3 * HDIM * HDIM;
        const bf16* iwl = wl + OFF_INW  + (size_t)i * 3 * HDIM * HDIM;
        const bf16* owh = wh + OFF_OUTW + (size_t)i * HDIM * HDIM;
        const bf16* owl = wl + OFF_OUTW + (size_t)i * HDIM * HDIM;
        const bf16* v1h = wh + OFF_VW1  + (size_t)i * FFD * HDIM;
        const bf16* v1l = wl + OFF_VW1  + (size_t)i * FFD * HDIM;
        const bf16* l1h = wh + OFF_LW1  + (size_t)i * FFD * HDIM;
        const bf16* l1l = wl + OFF_LW1  + (size_t)i * FFD * HDIM;
        const bf16* v2h = wh + OFF_VW2  + (size_t)i * HDIM * FFD;
        const bf16* v2l = wl + OFF_VW2  + (size_t)i * HDIM * FFD;
        const bf16* l2h = wh + OFF_LW2  + (size_t)i * HDIM * FFD;
        const bf16* l2l = wl + OFF_LW2  + (size_t)i * HDIM * FFD;
        const float* ib  = in_b  + (size_t)i * 3 * HDIM;
        const float* ob  = out_b + (size_t)i * HDIM;
        const float* g1  = ln1g + (size_t)i * HDIM;
        const float* be1 = ln1b + (size_t)i * HDIM;
        const float* g2  = ln2g + (size_t)i * HDIM;
        const float* be2 = ln2b + (size_t)i * HDIM;
        const float* vb1 = veb1 + (size_t)i * FFD;
        const float* vb2 = veb2 + (size_t)i * HDIM;
        const float* lb1 = leb1 + (size_t)i * FFD;
        const float* lb2 = leb2 + (size_t)i * HDIM;

        // QKV projection -> split bf16 (coalesced; V stays in natural layout)
        gemm_tc<<<dim3(18, 64), 256, SMEM_TOT>>>(MROWS, 3 * HDIM, HDIM,
            xh, xl, HDIM, 0, iwh, iwl, HDIM, ib,
            nullptr, qh, ql, 3 * HDIM, 0, 0);

        // fused attention: scores + softmax + P·V (V via ldmatrix.trans)
        flash_attn<<<dim3(4, 1, NB * NHEAD), 256, FA_SMEM>>>(qh, ql, bias, yh, yl);

        // out projection -> fp32
        gemm_tc<<<dim3(6, 64), 256, SMEM_TOT>>>(MROWS, HDIM, HDIM,
            yh, yl, HDIM, 0, owh, owl, HDIM, ob,
            attn, nullptr, nullptr, HDIM, 0, 0);

        ln_row<<<MROWS, 256>>>(x, attn, g1, be1, g1, be1, x, xh, xl);

        // dual-expert FFN (GELU) merged launches
        gemm_dual<<<dim3(24, 40, 2), 256, SMEM_TOT>>>(FFD, 1,
            3136, HDIM, xh, xl, HDIM, 1, v1h, v1l, vb1,
            5056, HDIM, xh, xl, HDIM, 2, l1h, l1l, lb1,
            nullptr, hh, hl, FFD, 1, 2);
        gemm_dual<<<dim3(6, 40, 2), 256, SMEM_TOT>>>(HDIM, 0,
            3136, FFD, hh, hl, FFD, 1, v2h, v2l, vb2,
            5056, FFD, hh, hl, FFD, 2, l2h, l2l, lb2,
            ffn, nullptr, nullptr, HDIM, 1, 2);

        // final layer LN writes straight into d_out; others into x
        float* lnOut = (i == NLAYER - 1) ? (float*)d_out : x;
        ln_row<<<MROWS, 256>>>(x, ffn, g2, be2, g2, be2, lnOut, xh, xl);
    }

    mask_tail<<<32, 256>>>(mask, (float*)d_out, out_size);
}